// round 1
// baseline (speedup 1.0000x reference)
#include <cuda_runtime.h>
#include <cuda_bf16.h>
#include <math.h>

// Problem constants (fixed by the reference).
#define BB 512
#define TT 128
#define FF 1024
#define HH 1024
#define NOUT 256
#define FOURH (4 * HH)
#define BT (BB * TT)          // 65536

// ---------------------------------------------------------------------------
// Scratch: device globals (no allocation allowed in kernel_launch).
// ---------------------------------------------------------------------------
__device__ float g_xw[(size_t)BT * FOURH];   // X @ W_x + b  (1 GiB)
__device__ float g_feats[(size_t)BT * HH];   // masked h outputs per (b,t) (256 MiB)
__device__ float g_z[(size_t)BB * FOURH];    // per-step recurrent gemm out
__device__ float g_c[(size_t)BB * HH];
__device__ float g_h[(size_t)BB * HH];

// ---------------------------------------------------------------------------
// Classic fp32 SGEMM: C[M,N] = A[M,K] @ B[K,N] (+ bias[N]).
// BM=BN=128, BK=8, TM=TN=8, 256 threads. Requires M%128==0, N%128==0, K%8==0.
// ---------------------------------------------------------------------------
template <bool BIAS>
__global__ __launch_bounds__(256, 2) void sgemm128(
    const float* __restrict__ A, const float* __restrict__ Bm,
    const float* __restrict__ bias, float* __restrict__ C,
    int M, int N, int K)
{
    constexpr int BM = 128, BN = 128, BK = 8, TM = 8, TN = 8;
    __shared__ float As[BK * BM];   // transposed: As[k][m]
    __shared__ float Bs[BK * BN];

    const int cRow = blockIdx.y;
    const int cCol = blockIdx.x;
    const int tid = threadIdx.x;

    const int threadRow = tid / (BN / TN);   // 0..15
    const int threadCol = tid % (BN / TN);   // 0..15

    A += (size_t)cRow * BM * K;
    Bm += (size_t)cCol * BN;
    C += (size_t)cRow * BM * N + cCol * BN;
    if (BIAS) bias += cCol * BN;

    const int innerRowA = tid / (BK / 4);    // 0..127
    const int innerColA = tid % (BK / 4);    // 0..1
    const int innerRowB = tid / (BN / 4);    // 0..7
    const int innerColB = tid % (BN / 4);    // 0..31

    float acc[TM * TN] = {0.0f};
    float regM[TM], regN[TN];

    for (int k0 = 0; k0 < K; k0 += BK) {
        float4 a4 = *(const float4*)&A[(size_t)innerRowA * K + innerColA * 4];
        As[(innerColA * 4 + 0) * BM + innerRowA] = a4.x;
        As[(innerColA * 4 + 1) * BM + innerRowA] = a4.y;
        As[(innerColA * 4 + 2) * BM + innerRowA] = a4.z;
        As[(innerColA * 4 + 3) * BM + innerRowA] = a4.w;
        *(float4*)&Bs[innerRowB * BN + innerColB * 4] =
            *(const float4*)&Bm[(size_t)innerRowB * N + innerColB * 4];
        __syncthreads();

        A += BK;
        Bm += (size_t)BK * N;

#pragma unroll
        for (int k = 0; k < BK; k++) {
            *(float4*)&regM[0] = *(const float4*)&As[k * BM + threadRow * TM];
            *(float4*)&regM[4] = *(const float4*)&As[k * BM + threadRow * TM + 4];
            *(float4*)&regN[0] = *(const float4*)&Bs[k * BN + threadCol * TN];
            *(float4*)&regN[4] = *(const float4*)&Bs[k * BN + threadCol * TN + 4];
#pragma unroll
            for (int i = 0; i < TM; i++)
#pragma unroll
                for (int j = 0; j < TN; j++)
                    acc[i * TN + j] += regM[i] * regN[j];
        }
        __syncthreads();
    }

#pragma unroll
    for (int i = 0; i < TM; i++) {
#pragma unroll
        for (int j = 0; j < TN; j += 4) {
            float4 v;
            v.x = acc[i * TN + j + 0];
            v.y = acc[i * TN + j + 1];
            v.z = acc[i * TN + j + 2];
            v.w = acc[i * TN + j + 3];
            const int col = threadCol * TN + j;
            if (BIAS) {
                v.x += bias[col + 0];
                v.y += bias[col + 1];
                v.z += bias[col + 2];
                v.w += bias[col + 3];
            }
            *(float4*)&C[(size_t)(threadRow * TM + i) * N + col] = v;
        }
    }
}

// ---------------------------------------------------------------------------
// State init: c,h <- c_in,h_in
// ---------------------------------------------------------------------------
__global__ void init_state(const float* __restrict__ c_in,
                           const float* __restrict__ h_in)
{
    int i = blockIdx.x * blockDim.x + threadIdx.x;
    if (i < BB * HH) {
        g_c[i] = c_in[i];
        g_h[i] = h_in[i];
    }
}

__device__ __forceinline__ float sigmoidf_(float x) {
    return 1.0f / (1.0f + expf(-x));
}

// ---------------------------------------------------------------------------
// LSTM cell elementwise step (gate order i, j, f, o; forget_bias = 1).
// z = g_z (h @ W_h) + g_xw row (x @ W_x + b). Masked dynamic_rnn semantics.
// ---------------------------------------------------------------------------
__global__ __launch_bounds__(256) void lstm_cell(int t, const int* __restrict__ seq_lens)
{
    int idx = blockIdx.x * blockDim.x + threadIdx.x;   // 0 .. B*H-1
    if (idx >= BB * HH) return;
    int b = idx / HH;
    int hx = idx % HH;

    const size_t zrow = (size_t)b * FOURH;
    const size_t xrow = ((size_t)b * TT + t) * FOURH;

    float zi = g_z[zrow + 0 * HH + hx] + g_xw[xrow + 0 * HH + hx];
    float zj = g_z[zrow + 1 * HH + hx] + g_xw[xrow + 1 * HH + hx];
    float zf = g_z[zrow + 2 * HH + hx] + g_xw[xrow + 2 * HH + hx];
    float zo = g_z[zrow + 3 * HH + hx] + g_xw[xrow + 3 * HH + hx];

    float c = g_c[idx];
    float new_c = c * sigmoidf_(zf + 1.0f) + sigmoidf_(zi) * tanhf(zj);
    float new_h = tanhf(new_c) * sigmoidf_(zo);

    bool m = (t < seq_lens[b]);
    g_c[idx] = m ? new_c : c;
    float h_prev = g_h[idx];
    g_h[idx] = m ? new_h : h_prev;
    g_feats[((size_t)b * TT + t) * HH + hx] = m ? new_h : 0.0f;
}

// ---------------------------------------------------------------------------
// kernel_launch: graph-capturable, allocation-free.
// Inputs: 0 padded_inputs [B*T,F] f32, 1 seq_lens [B] i32, 2 c_in [B,H],
//         3 h_in [B,H], 4 W [F+H,4H], 5 b [4H], 6 W_out [H,NOUT], 7 b_out [NOUT]
// Output: logits [B*T, NOUT] f32
// ---------------------------------------------------------------------------
extern "C" void kernel_launch(void* const* d_in, const int* in_sizes, int n_in,
                              void* d_out, int out_size)
{
    const float* X    = (const float*)d_in[0];
    const int*   seq  = (const int*)d_in[1];
    const float* c_in = (const float*)d_in[2];
    const float* h_in = (const float*)d_in[3];
    const float* W    = (const float*)d_in[4];
    const float* bias = (const float*)d_in[5];
    const float* Wout = (const float*)d_in[6];
    const float* bout = (const float*)d_in[7];
    float* out = (float*)d_out;

    float *p_xw, *p_feats, *p_z, *p_h;
    cudaGetSymbolAddress((void**)&p_xw, g_xw);
    cudaGetSymbolAddress((void**)&p_feats, g_feats);
    cudaGetSymbolAddress((void**)&p_z, g_z);
    cudaGetSymbolAddress((void**)&p_h, g_h);

    // 1) init state
    init_state<<<(BB * HH + 255) / 256, 256>>>(c_in, h_in);

    // 2) XW = X @ W[0:F,:] + b    ([65536,1024] @ [1024,4096])
    {
        dim3 grid(FOURH / 128, BT / 128);
        sgemm128<true><<<grid, 256>>>(X, W, bias, p_xw, BT, FOURH, FF);
    }

    // 3) sequential recurrence
    const float* Wh = W + (size_t)FF * FOURH;   // rows F..F+H-1
    for (int t = 0; t < TT; t++) {
        dim3 grid(FOURH / 128, BB / 128);       // (32, 4)
        sgemm128<false><<<grid, 256>>>(p_h, Wh, nullptr, p_z, BB, FOURH, HH);
        lstm_cell<<<(BB * HH + 255) / 256, 256>>>(t, seq);
    }

    // 4) head: out = feats @ W_out + b_out   ([65536,1024] @ [1024,256])
    {
        dim3 grid(NOUT / 128, BT / 128);        // (2, 512)
        sgemm128<true><<<grid, 256>>>(p_feats, Wout, bout, out, BT, NOUT, HH);
    }
}

// round 3
// speedup vs baseline: 1.8660x; 1.8660x over previous
#include <cuda_runtime.h>
#include <cuda_bf16.h>
#include <math.h>
#include <stdint.h>

#define BB 512
#define TT 128
#define FF 1024
#define HH 1024
#define NOUT 256
#define FOURH 4096
#define BT 65536

typedef __nv_bfloat16 bf16;

// ---------------------------------------------------------------------------
// Device-global scratch (no allocations allowed anywhere).
// ---------------------------------------------------------------------------
__device__ float g_xw[(size_t)BT * FOURH];          // X @ Wx + b (fp32)
__device__ float g_z[(size_t)BB * FOURH];           // h @ Wh per step
__device__ float g_c[BB * HH];
__device__ float g_h[BB * HH];
__device__ bf16  g_x_hi[(size_t)BT * FF];
__device__ bf16  g_x_lo[(size_t)BT * FF];
__device__ bf16  g_f_hi[(size_t)BT * HH];
__device__ bf16  g_f_lo[(size_t)BT * HH];
__device__ bf16  g_h_hi[BB * HH];
__device__ bf16  g_h_lo[BB * HH];
__device__ bf16  g_wx_hi[(size_t)FOURH * FF];       // Wx^T [4H,F] K-major
__device__ bf16  g_wx_lo[(size_t)FOURH * FF];
__device__ bf16  g_wh_hi[(size_t)FOURH * HH];       // Wh^T [4H,H]
__device__ bf16  g_wh_lo[(size_t)FOURH * HH];
__device__ bf16  g_wo_hi[NOUT * HH];                // Wout^T [NOUT,H]
__device__ bf16  g_wo_lo[NOUT * HH];

// ---------------------------------------------------------------------------
// Baseline-PTX building blocks (legal on plain sm_103 target)
// ---------------------------------------------------------------------------
__device__ __forceinline__ uint32_t smem_u32(const void* p) {
    uint32_t a;
    asm("{ .reg .u64 t; cvta.to.shared.u64 t, %1; cvt.u32.u64 %0, t; }"
        : "=r"(a) : "l"(p));
    return a;
}

__device__ __forceinline__ void cp16(uint32_t dst, const void* src) {
    asm volatile("cp.async.cg.shared.global [%0], [%1], 16;"
                 :: "r"(dst), "l"(src) : "memory");
}

__device__ __forceinline__ void ldsm4(uint32_t* r, uint32_t addr) {
    asm volatile("ldmatrix.sync.aligned.m8n8.x4.shared.b16 {%0,%1,%2,%3}, [%4];"
                 : "=r"(r[0]), "=r"(r[1]), "=r"(r[2]), "=r"(r[3]) : "r"(addr));
}

__device__ __forceinline__ void mma16816(float* d, const uint32_t* a, const uint32_t* b) {
    asm volatile(
        "mma.sync.aligned.m16n8k16.row.col.f32.bf16.bf16.f32 "
        "{%0,%1,%2,%3}, {%4,%5,%6,%7}, {%8,%9}, {%0,%1,%2,%3};"
        : "+f"(d[0]), "+f"(d[1]), "+f"(d[2]), "+f"(d[3])
        : "r"(a[0]), "r"(a[1]), "r"(a[2]), "r"(a[3]), "r"(b[0]), "r"(b[1]));
}

// ---------------------------------------------------------------------------
// GEMM: C[M,N] = Ah@Bh^T + Ah@Bl^T + Al@Bh^T (+ bias)
// A: [M,K] bf16 row-major (K-major). B: [N,K] bf16 (K-major). C fp32 [M,N].
// BM=BN=128, BK=32. 256 threads, 8 warps (2x4), warp tile 64x32.
// 4-stage cp.async pipeline. SMEM rows: 32 halves padded to 80B (conflict-free).
// ---------------------------------------------------------------------------
#define ROWB 80                       // bytes per smem row (32 halves + pad)
#define OP_BYTES (128 * ROWB)         // 10240 per operand tile
#define OFF_AH 0
#define OFF_AL (1 * OP_BYTES)
#define OFF_BH (2 * OP_BYTES)
#define OFF_BL (3 * OP_BYTES)
#define STAGE_BYTES (4 * OP_BYTES)    // 40960
#define NSTAGE 4
#define GEMM_SMEM (NSTAGE * STAGE_BYTES)  // 163840

__device__ __forceinline__ void load_stage(
    uint32_t stg, const bf16* __restrict__ Ah, const bf16* __restrict__ Al,
    const bf16* __restrict__ Bh, const bf16* __restrict__ Bl,
    int m0, int n0, int k0, int K, int tid)
{
#pragma unroll
    for (int i = 0; i < 2; i++) {
        const int c = tid + i * 256;
        const int row = c >> 2;
        const int seg = c & 3;
        const uint32_t soff = (uint32_t)(row * ROWB + seg * 16);
        const size_t ga = (size_t)(m0 + row) * K + k0 + seg * 8;
        const size_t gb = (size_t)(n0 + row) * K + k0 + seg * 8;
        cp16(stg + OFF_AH + soff, Ah + ga);
        cp16(stg + OFF_AL + soff, Al + ga);
        cp16(stg + OFF_BH + soff, Bh + gb);
        cp16(stg + OFF_BL + soff, Bl + gb);
    }
}

__global__ __launch_bounds__(256, 1)
void gemm_bf16x3(const bf16* __restrict__ Ah, const bf16* __restrict__ Al,
                 const bf16* __restrict__ Bh, const bf16* __restrict__ Bl,
                 const float* __restrict__ bias, float* __restrict__ C,
                 int N, int K)
{
    extern __shared__ char smem_raw[];
    const uint32_t SM = smem_u32(smem_raw);

    const int tid  = threadIdx.x;
    const int lane = tid & 31;
    const int wid  = tid >> 5;
    const int wm   = wid & 1;          // 0..1 (64-row halves)
    const int wn   = wid >> 1;         // 0..3 (32-col quarters)
    const int m0 = blockIdx.y * 128;
    const int n0 = blockIdx.x * 128;
    const int NC = K >> 5;             // 32-element K chunks

    float acc[4][4][4];
#pragma unroll
    for (int a = 0; a < 4; a++)
#pragma unroll
        for (int b = 0; b < 4; b++)
#pragma unroll
            for (int cc = 0; cc < 4; cc++) acc[a][b][cc] = 0.0f;

    // prologue: fill NSTAGE-1 stages
#pragma unroll
    for (int s = 0; s < NSTAGE - 1; s++) {
        load_stage(SM + s * STAGE_BYTES, Ah, Al, Bh, Bl, m0, n0, s * 32, K, tid);
        asm volatile("cp.async.commit_group;" ::: "memory");
    }

    // fragment addressing (constant across iterations except stage base)
    const int arow = wm * 64 + (lane & 15);
    const uint32_t akoff = (uint32_t)((lane >> 4) * 16);       // bytes within k-slice
    const int bsel = lane >> 3;
    const int bn = wn * 32 + ((bsel >> 1) << 3) + (lane & 7);
    const uint32_t bkoff = (uint32_t)((bsel & 1) * 16);

    for (int it = 0; it < NC; it++) {
        asm volatile("cp.async.wait_group %0;" :: "n"(NSTAGE - 2) : "memory");
        __syncthreads();

        const uint32_t stg = SM + (uint32_t)(it & (NSTAGE - 1)) * STAGE_BYTES;

#pragma unroll
        for (int ks = 0; ks < 2; ks++) {
            uint32_t ah[4][4], al[4][4], bh[4][2], bl[4][2];
            const uint32_t ak = (uint32_t)(ks * 32) + akoff;
#pragma unroll
            for (int mt = 0; mt < 4; mt++) {
                const uint32_t ad = stg + (uint32_t)((arow + mt * 16) * ROWB) + ak;
                ldsm4(ah[mt], ad + OFF_AH);
                ldsm4(al[mt], ad + OFF_AL);
            }
            const uint32_t bk = (uint32_t)(ks * 32) + bkoff;
#pragma unroll
            for (int np = 0; np < 2; np++) {
                const uint32_t bd = stg + (uint32_t)((bn + np * 16) * ROWB) + bk;
                uint32_t t[4];
                ldsm4(t, bd + OFF_BH);
                bh[2 * np][0] = t[0]; bh[2 * np][1] = t[1];
                bh[2 * np + 1][0] = t[2]; bh[2 * np + 1][1] = t[3];
                ldsm4(t, bd + OFF_BL);
                bl[2 * np][0] = t[0]; bl[2 * np][1] = t[1];
                bl[2 * np + 1][0] = t[2]; bl[2 * np + 1][1] = t[3];
            }
#pragma unroll
            for (int mt = 0; mt < 4; mt++)
#pragma unroll
                for (int nt = 0; nt < 4; nt++) {
                    mma16816(acc[mt][nt], ah[mt], bh[nt]);
                    mma16816(acc[mt][nt], ah[mt], bl[nt]);
                    mma16816(acc[mt][nt], al[mt], bh[nt]);
                }
        }
        __syncthreads();

        const int nx = it + NSTAGE - 1;
        if (nx < NC)
            load_stage(SM + (uint32_t)(nx & (NSTAGE - 1)) * STAGE_BYTES,
                       Ah, Al, Bh, Bl, m0, n0, nx * 32, K, tid);
        asm volatile("cp.async.commit_group;" ::: "memory");
    }

    // epilogue: direct register -> global, fused bias
    const int colq = (lane & 3) * 2;
    const int rowq = lane >> 2;
#pragma unroll
    for (int nt = 0; nt < 4; nt++) {
        const int col = n0 + wn * 32 + nt * 8 + colq;
        float bx = 0.f, by = 0.f;
        if (bias) { float2 bv = *(const float2*)(bias + col); bx = bv.x; by = bv.y; }
#pragma unroll
        for (int mt = 0; mt < 4; mt++) {
            const int r0 = m0 + wm * 64 + mt * 16 + rowq;
            float2 v0 = make_float2(acc[mt][nt][0] + bx, acc[mt][nt][1] + by);
            float2 v1 = make_float2(acc[mt][nt][2] + bx, acc[mt][nt][3] + by);
            *(float2*)(C + (size_t)r0 * N + col) = v0;
            *(float2*)(C + (size_t)(r0 + 8) * N + col) = v1;
        }
    }
}

// ---------------------------------------------------------------------------
// Conversion / transpose / cell kernels
// ---------------------------------------------------------------------------
__device__ __forceinline__ void split1(float v, bf16& hi, bf16& lo) {
    hi = __float2bfloat16(v);
    lo = __float2bfloat16(v - __bfloat162float(hi));
}

__global__ void init_state(const float* __restrict__ c_in, const float* __restrict__ h_in)
{
    int i = blockIdx.x * blockDim.x + threadIdx.x;
    if (i < BB * HH) {
        g_c[i] = c_in[i];
        float h = h_in[i];
        g_h[i] = h;
        split1(h, g_h_hi[i], g_h_lo[i]);
    }
}

__global__ __launch_bounds__(256) void convert_x(const float* __restrict__ x)
{
    size_t i4 = (size_t)blockIdx.x * 256 + threadIdx.x;
    float4 v = *(const float4*)(x + i4 * 4);
    union { bf16 h[4]; uint2 u; } H, L;
    split1(v.x, H.h[0], L.h[0]);
    split1(v.y, H.h[1], L.h[1]);
    split1(v.z, H.h[2], L.h[2]);
    split1(v.w, H.h[3], L.h[3]);
    *(uint2*)(g_x_hi + i4 * 4) = H.u;
    *(uint2*)(g_x_lo + i4 * 4) = L.u;
}

// in: [K,N] fp32 row-major -> out: [N,K] bf16 hi/lo
__global__ void transpose_split(const float* __restrict__ in, bf16* __restrict__ oh,
                                bf16* __restrict__ ol, int K, int N)
{
    __shared__ float tile[32][33];
    const int kb = blockIdx.y * 32;
    const int nb = blockIdx.x * 32;
    const int tx = threadIdx.x;
    for (int r = threadIdx.y; r < 32; r += 8)
        tile[r][tx] = in[(size_t)(kb + r) * N + nb + tx];
    __syncthreads();
    for (int rr = threadIdx.y; rr < 32; rr += 8) {
        float v = tile[tx][rr];
        bf16 hi, lo;
        split1(v, hi, lo);
        const size_t o = (size_t)(nb + rr) * K + kb + tx;
        oh[o] = hi;
        ol[o] = lo;
    }
}

__device__ __forceinline__ float sigf(float x) { return 1.0f / (1.0f + expf(-x)); }

__global__ __launch_bounds__(256) void lstm_cell_k(int t, const int* __restrict__ seq)
{
    const int i4 = blockIdx.x * 256 + threadIdx.x;   // 0 .. BB*HH/4-1
    const int b  = i4 >> 8;
    const int hx = (i4 & 255) << 2;
    const size_t zr = (size_t)b * FOURH + hx;
    const size_t xr = ((size_t)b * TT + t) * FOURH + hx;

    float4 vi = *(const float4*)(g_z + zr);
    float4 wi = *(const float4*)(g_xw + xr);
    float4 vj = *(const float4*)(g_z + zr + HH);
    float4 wj = *(const float4*)(g_xw + xr + HH);
    float4 vf = *(const float4*)(g_z + zr + 2 * HH);
    float4 wf = *(const float4*)(g_xw + xr + 2 * HH);
    float4 vo = *(const float4*)(g_z + zr + 3 * HH);
    float4 wo = *(const float4*)(g_xw + xr + 3 * HH);

    const size_t si = (size_t)b * HH + hx;
    float4 c4 = *(const float4*)(g_c + si);
    float4 h4 = *(const float4*)(g_h + si);
    const bool m = t < seq[b];
    float4 fe;

#define GATE(K_) { \
    float ii = vi.K_ + wi.K_; float jj = vj.K_ + wj.K_; \
    float fg = vf.K_ + wf.K_; float oo = vo.K_ + wo.K_; \
    float cc = c4.K_; \
    float ncell = cc * sigf(fg + 1.0f) + sigf(ii) * tanhf(jj); \
    float nhid  = tanhf(ncell) * sigf(oo); \
    c4.K_ = m ? ncell : cc; \
    h4.K_ = m ? nhid : h4.K_; \
    fe.K_ = m ? nhid : 0.0f; }
    GATE(x) GATE(y) GATE(z) GATE(w)
#undef GATE

    *(float4*)(g_c + si) = c4;
    *(float4*)(g_h + si) = h4;

    union { bf16 h[4]; uint2 u; } H, L;
    split1(h4.x, H.h[0], L.h[0]); split1(h4.y, H.h[1], L.h[1]);
    split1(h4.z, H.h[2], L.h[2]); split1(h4.w, H.h[3], L.h[3]);
    *(uint2*)(g_h_hi + si) = H.u;
    *(uint2*)(g_h_lo + si) = L.u;

    const size_t fo = ((size_t)b * TT + t) * HH + hx;
    split1(fe.x, H.h[0], L.h[0]); split1(fe.y, H.h[1], L.h[1]);
    split1(fe.z, H.h[2], L.h[2]); split1(fe.w, H.h[3], L.h[3]);
    *(uint2*)(g_f_hi + fo) = H.u;
    *(uint2*)(g_f_lo + fo) = L.u;
}

// ---------------------------------------------------------------------------
// kernel_launch
// ---------------------------------------------------------------------------
extern "C" void kernel_launch(void* const* d_in, const int* in_sizes, int n_in,
                              void* d_out, int out_size)
{
    const float* X    = (const float*)d_in[0];
    const int*   seq  = (const int*)d_in[1];
    const float* c_in = (const float*)d_in[2];
    const float* h_in = (const float*)d_in[3];
    const float* W    = (const float*)d_in[4];
    const float* bias = (const float*)d_in[5];
    const float* Wout = (const float*)d_in[6];
    const float* bout = (const float*)d_in[7];
    float* out = (float*)d_out;

    float *p_xw, *p_z;
    bf16 *p_xh, *p_xl, *p_fh, *p_fl, *p_hh, *p_hl;
    bf16 *p_wxh, *p_wxl, *p_whh, *p_whl, *p_woh, *p_wol;
    cudaGetSymbolAddress((void**)&p_xw, g_xw);
    cudaGetSymbolAddress((void**)&p_z, g_z);
    cudaGetSymbolAddress((void**)&p_xh, g_x_hi);
    cudaGetSymbolAddress((void**)&p_xl, g_x_lo);
    cudaGetSymbolAddress((void**)&p_fh, g_f_hi);
    cudaGetSymbolAddress((void**)&p_fl, g_f_lo);
    cudaGetSymbolAddress((void**)&p_hh, g_h_hi);
    cudaGetSymbolAddress((void**)&p_hl, g_h_lo);
    cudaGetSymbolAddress((void**)&p_wxh, g_wx_hi);
    cudaGetSymbolAddress((void**)&p_wxl, g_wx_lo);
    cudaGetSymbolAddress((void**)&p_whh, g_wh_hi);
    cudaGetSymbolAddress((void**)&p_whl, g_wh_lo);
    cudaGetSymbolAddress((void**)&p_woh, g_wo_hi);
    cudaGetSymbolAddress((void**)&p_wol, g_wo_lo);

    cudaFuncSetAttribute(gemm_bf16x3, cudaFuncAttributeMaxDynamicSharedMemorySize, GEMM_SMEM);

    // 1) state init + operand preparation
    init_state<<<(BB * HH + 255) / 256, 256>>>(c_in, h_in);
    convert_x<<<(int)((size_t)BT * FF / 4 / 256), 256>>>(X);
    transpose_split<<<dim3(FOURH / 32, FF / 32), dim3(32, 8)>>>(W, p_wxh, p_wxl, FF, FOURH);
    transpose_split<<<dim3(FOURH / 32, HH / 32), dim3(32, 8)>>>(W + (size_t)FF * FOURH, p_whh, p_whl, HH, FOURH);
    transpose_split<<<dim3(NOUT / 32, HH / 32), dim3(32, 8)>>>(Wout, p_woh, p_wol, HH, NOUT);

    // 2) XW = X @ Wx + b   ([65536,1024] x [1024,4096])
    gemm_bf16x3<<<dim3(FOURH / 128, BT / 128), 256, GEMM_SMEM>>>(
        p_xh, p_xl, p_wxh, p_wxl, bias, p_xw, FOURH, FF);

    // 3) recurrence
    for (int t = 0; t < TT; t++) {
        gemm_bf16x3<<<dim3(FOURH / 128, BB / 128), 256, GEMM_SMEM>>>(
            p_hh, p_hl, p_whh, p_whl, nullptr, p_z, FOURH, HH);
        lstm_cell_k<<<BB * HH / 4 / 256, 256>>>(t, seq);
    }

    // 4) head: logits = feats @ Wout + b_out
    gemm_bf16x3<<<dim3(NOUT / 128, BT / 128), 256, GEMM_SMEM>>>(
        p_fh, p_fl, p_woh, p_wol, bout, out, NOUT, HH);
}

// round 4
// speedup vs baseline: 2.7203x; 1.4578x over previous
#include <cuda_runtime.h>
#include <cuda_bf16.h>
#include <math.h>
#include <stdint.h>

#define BB 512
#define TT 128
#define FF 1024
#define HH 1024
#define NOUT 256
#define FOURH 4096
#define BT 65536

typedef __nv_bfloat16 bf16;

// ---------------------------------------------------------------------------
// Device-global scratch
// ---------------------------------------------------------------------------
__device__ float g_xw[(size_t)BT * FOURH];     // X @ Wx + b, gate-interleaved cols
__device__ float g_c[BB * HH];
__device__ float g_h[BB * HH];
__device__ float g_bias[FOURH];                // permuted bias
__device__ bf16  g_x_hi[(size_t)BT * FF];
__device__ bf16  g_x_lo[(size_t)BT * FF];
__device__ bf16  g_f_hi[(size_t)BT * HH];
__device__ bf16  g_f_lo[(size_t)BT * HH];
__device__ bf16  g_h_hi[BB * HH];
__device__ bf16  g_h_lo[BB * HH];
__device__ bf16  g_wx_hi[(size_t)FOURH * FF];  // Wx^T [4H,F] K-major, interleaved rows
__device__ bf16  g_wx_lo[(size_t)FOURH * FF];
__device__ bf16  g_wh_hi[(size_t)FOURH * HH];  // Wh^T interleaved rows
__device__ bf16  g_wh_lo[(size_t)FOURH * HH];
__device__ bf16  g_wo_hi[NOUT * HH];
__device__ bf16  g_wo_lo[NOUT * HH];

// ---------------------------------------------------------------------------
// Baseline-PTX helpers (legal on plain sm_103 target)
// ---------------------------------------------------------------------------
__device__ __forceinline__ uint32_t smem_u32(const void* p) {
    uint32_t a;
    asm("{ .reg .u64 t; cvta.to.shared.u64 t, %1; cvt.u32.u64 %0, t; }"
        : "=r"(a) : "l"(p));
    return a;
}
__device__ __forceinline__ void cp16(uint32_t dst, const void* src) {
    asm volatile("cp.async.cg.shared.global [%0], [%1], 16;"
                 :: "r"(dst), "l"(src) : "memory");
}
__device__ __forceinline__ void ldsm4(uint32_t* r, uint32_t addr) {
    asm volatile("ldmatrix.sync.aligned.m8n8.x4.shared.b16 {%0,%1,%2,%3}, [%4];"
                 : "=r"(r[0]), "=r"(r[1]), "=r"(r[2]), "=r"(r[3]) : "r"(addr));
}
__device__ __forceinline__ void mma16816(float* d, const uint32_t* a, const uint32_t* b) {
    asm volatile(
        "mma.sync.aligned.m16n8k16.row.col.f32.bf16.bf16.f32 "
        "{%0,%1,%2,%3}, {%4,%5,%6,%7}, {%8,%9}, {%0,%1,%2,%3};"
        : "+f"(d[0]), "+f"(d[1]), "+f"(d[2]), "+f"(d[3])
        : "r"(a[0]), "r"(a[1]), "r"(a[2]), "r"(a[3]), "r"(b[0]), "r"(b[1]));
}

// ---------------------------------------------------------------------------
// Shared GEMM tile machinery. BM=BN=128, BK=32, 256 threads (8 warps 2x4).
// ---------------------------------------------------------------------------
#define ROWB 80
#define OP_BYTES (128 * ROWB)
#define OFF_AH 0
#define OFF_AL (1 * OP_BYTES)
#define OFF_BH (2 * OP_BYTES)
#define OFF_BL (3 * OP_BYTES)
#define STAGE_BYTES (4 * OP_BYTES)
#define NSTAGE 4
#define GEMM_SMEM (NSTAGE * STAGE_BYTES)   // 163840

__device__ __forceinline__ void load_stage(
    uint32_t stg, const bf16* __restrict__ Ah, const bf16* __restrict__ Al,
    const bf16* __restrict__ Bh, const bf16* __restrict__ Bl,
    int m0, int n0, int k0, int K, int tid)
{
#pragma unroll
    for (int i = 0; i < 2; i++) {
        const int c = tid + i * 256;
        const int row = c >> 2;
        const int seg = c & 3;
        const uint32_t soff = (uint32_t)(row * ROWB + seg * 16);
        const size_t ga = (size_t)(m0 + row) * K + k0 + seg * 8;
        const size_t gb = (size_t)(n0 + row) * K + k0 + seg * 8;
        cp16(stg + OFF_AH + soff, Ah + ga);
        cp16(stg + OFF_AL + soff, Al + ga);
        cp16(stg + OFF_BH + soff, Bh + gb);
        cp16(stg + OFF_BL + soff, Bl + gb);
    }
}

// mainloop: accumulates 128x128 x3-term into acc. One barrier per chunk;
// loads issued before compute for overlap.
__device__ __forceinline__ void gemm_mainloop(
    uint32_t SM, const bf16* __restrict__ Ah, const bf16* __restrict__ Al,
    const bf16* __restrict__ Bh, const bf16* __restrict__ Bl,
    int m0, int n0, int K, int tid, float acc[4][4][4])
{
    const int lane = tid & 31;
    const int wid  = tid >> 5;
    const int wm   = wid & 1;
    const int wn   = wid >> 1;
    const int NC = K >> 5;

#pragma unroll
    for (int s = 0; s < NSTAGE - 1; s++) {
        load_stage(SM + s * STAGE_BYTES, Ah, Al, Bh, Bl, m0, n0, s * 32, K, tid);
        asm volatile("cp.async.commit_group;" ::: "memory");
    }

    const int arow = wm * 64 + (lane & 15);
    const uint32_t akoff = (uint32_t)((lane >> 4) * 16);
    const int bsel = lane >> 3;
    const int bn = wn * 32 + ((bsel >> 1) << 3) + (lane & 7);
    const uint32_t bkoff = (uint32_t)((bsel & 1) * 16);

    for (int it = 0; it < NC; it++) {
        asm volatile("cp.async.wait_group %0;" :: "n"(NSTAGE - 2) : "memory");
        __syncthreads();

        const int nx = it + NSTAGE - 1;
        if (nx < NC)
            load_stage(SM + (uint32_t)(nx & (NSTAGE - 1)) * STAGE_BYTES,
                       Ah, Al, Bh, Bl, m0, n0, nx * 32, K, tid);
        asm volatile("cp.async.commit_group;" ::: "memory");

        const uint32_t stg = SM + (uint32_t)(it & (NSTAGE - 1)) * STAGE_BYTES;
#pragma unroll
        for (int ks = 0; ks < 2; ks++) {
            uint32_t ah[4][4], al[4][4], bh[4][2], bl[4][2];
            const uint32_t ak = (uint32_t)(ks * 32) + akoff;
#pragma unroll
            for (int mt = 0; mt < 4; mt++) {
                const uint32_t ad = stg + (uint32_t)((arow + mt * 16) * ROWB) + ak;
                ldsm4(ah[mt], ad + OFF_AH);
                ldsm4(al[mt], ad + OFF_AL);
            }
            const uint32_t bk = (uint32_t)(ks * 32) + bkoff;
#pragma unroll
            for (int np = 0; np < 2; np++) {
                const uint32_t bd = stg + (uint32_t)((bn + np * 16) * ROWB) + bk;
                uint32_t tr[4];
                ldsm4(tr, bd + OFF_BH);
                bh[2 * np][0] = tr[0]; bh[2 * np][1] = tr[1];
                bh[2 * np + 1][0] = tr[2]; bh[2 * np + 1][1] = tr[3];
                ldsm4(tr, bd + OFF_BL);
                bl[2 * np][0] = tr[0]; bl[2 * np][1] = tr[1];
                bl[2 * np + 1][0] = tr[2]; bl[2 * np + 1][1] = tr[3];
            }
#pragma unroll
            for (int mt = 0; mt < 4; mt++)
#pragma unroll
                for (int nt = 0; nt < 4; nt++) {
                    mma16816(acc[mt][nt], ah[mt], bh[nt]);
                    mma16816(acc[mt][nt], ah[mt], bl[nt]);
                    mma16816(acc[mt][nt], al[mt], bh[nt]);
                }
        }
    }
}

// ---------------------------------------------------------------------------
// Plain GEMM (XW and head): C = A@B^T (+bias)
// ---------------------------------------------------------------------------
__global__ __launch_bounds__(256, 1)
void gemm_bf16x3(const bf16* __restrict__ Ah, const bf16* __restrict__ Al,
                 const bf16* __restrict__ Bh, const bf16* __restrict__ Bl,
                 const float* __restrict__ bias, float* __restrict__ C,
                 int N, int K)
{
    extern __shared__ char smem_raw[];
    const uint32_t SM = smem_u32(smem_raw);
    const int tid  = threadIdx.x;
    const int lane = tid & 31;
    const int wid  = tid >> 5;
    const int wm   = wid & 1;
    const int wn   = wid >> 1;
    const int m0 = blockIdx.y * 128;
    const int n0 = blockIdx.x * 128;

    float acc[4][4][4];
#pragma unroll
    for (int a = 0; a < 4; a++)
#pragma unroll
        for (int b = 0; b < 4; b++)
#pragma unroll
            for (int cc = 0; cc < 4; cc++) acc[a][b][cc] = 0.0f;

    gemm_mainloop(SM, Ah, Al, Bh, Bl, m0, n0, K, tid, acc);

    const int colq = (lane & 3) * 2;
    const int rowq = lane >> 2;
#pragma unroll
    for (int nt = 0; nt < 4; nt++) {
        const int col = n0 + wn * 32 + nt * 8 + colq;
        float bx = 0.f, by = 0.f;
        if (bias) { float2 bv = *(const float2*)(bias + col); bx = bv.x; by = bv.y; }
#pragma unroll
        for (int mt = 0; mt < 4; mt++) {
            const int r0 = m0 + wm * 64 + mt * 16 + rowq;
            *(float2*)(C + (size_t)r0 * N + col) =
                make_float2(acc[mt][nt][0] + bx, acc[mt][nt][1] + by);
            *(float2*)(C + (size_t)(r0 + 8) * N + col) =
                make_float2(acc[mt][nt][2] + bx, acc[mt][nt][3] + by);
        }
    }
}

// ---------------------------------------------------------------------------
// Fused recurrent step: z = h @ Wh^T (interleaved cols), + xw, LSTM cell,
// masked state update, bf16 splits. One kernel per timestep.
// ---------------------------------------------------------------------------
__device__ __forceinline__ float sigf(float x) { return 1.0f / (1.0f + expf(-x)); }
__device__ __forceinline__ void split1(float v, bf16& hi, bf16& lo) {
    hi = __float2bfloat16(v);
    lo = __float2bfloat16(v - __bfloat162float(hi));
}

#define ZPITCH 132

__global__ __launch_bounds__(256, 1)
void lstm_step_fused(int t, const int* __restrict__ seq)
{
    extern __shared__ char smem_raw[];
    const uint32_t SM = smem_u32(smem_raw);
    float* zs = (float*)smem_raw;           // reused after mainloop: 128 x ZPITCH
    const int tid  = threadIdx.x;
    const int lane = tid & 31;
    const int wid  = tid >> 5;
    const int wm   = wid & 1;
    const int wn   = wid >> 1;
    const int m0 = blockIdx.y * 128;        // batch offset
    const int n0 = blockIdx.x * 128;        // interleaved gate-col offset

    float acc[4][4][4];
#pragma unroll
    for (int a = 0; a < 4; a++)
#pragma unroll
        for (int b = 0; b < 4; b++)
#pragma unroll
            for (int cc = 0; cc < 4; cc++) acc[a][b][cc] = 0.0f;

    gemm_mainloop(SM, g_h_hi, g_h_lo, g_wh_hi, g_wh_lo, m0, n0, HH, tid, acc);

    __syncthreads();   // all warps done reading stage smem

    // acc -> smem z tile
    const int colq = (lane & 3) * 2;
    const int rowq = lane >> 2;
#pragma unroll
    for (int nt = 0; nt < 4; nt++) {
        const int col = wn * 32 + nt * 8 + colq;
#pragma unroll
        for (int mt = 0; mt < 4; mt++) {
            const int r0 = wm * 64 + mt * 16 + rowq;
            *(float2*)&zs[r0 * ZPITCH + col] = make_float2(acc[mt][nt][0], acc[mt][nt][1]);
            *(float2*)&zs[(r0 + 8) * ZPITCH + col] = make_float2(acc[mt][nt][2], acc[mt][nt][3]);
        }
    }
    __syncthreads();

    // cell epilogue: 128 rows x 32 units per CTA
#pragma unroll
    for (int i = 0; i < 16; i++) {
        const int idx = i * 256 + tid;
        const int r = idx >> 5;            // 0..127
        const int u = idx & 31;            // 0..31
        const int b = m0 + r;
        const int hx = (n0 >> 2) + u;

        float4 z4 = *(float4*)&zs[r * ZPITCH + 4 * u];
        float4 x4 = *(const float4*)(g_xw + ((size_t)b * TT + t) * FOURH + n0 + 4 * u);

        const float zi = z4.x + x4.x;
        const float zj = z4.y + x4.y;
        const float zf = z4.z + x4.z;
        const float zo = z4.w + x4.w;

        const size_t si = (size_t)b * HH + hx;
        const float c = g_c[si];
        const float hprev = g_h[si];
        const bool m = t < seq[b];

        const float nc = c * sigf(zf + 1.0f) + sigf(zi) * tanhf(zj);
        const float nh = tanhf(nc) * sigf(zo);

        const float co = m ? nc : c;
        const float ho = m ? nh : hprev;
        const float fe = m ? nh : 0.0f;

        g_c[si] = co;
        g_h[si] = ho;
        bf16 hi, lo;
        split1(ho, hi, lo);
        g_h_hi[si] = hi;
        g_h_lo[si] = lo;
        const size_t fo = ((size_t)b * TT + t) * HH + hx;
        split1(fe, hi, lo);
        g_f_hi[fo] = hi;
        g_f_lo[fo] = lo;
    }
}

// ---------------------------------------------------------------------------
// Prep kernels
// ---------------------------------------------------------------------------
__global__ void init_state(const float* __restrict__ c_in, const float* __restrict__ h_in)
{
    int i = blockIdx.x * blockDim.x + threadIdx.x;
    if (i < BB * HH) {
        g_c[i] = c_in[i];
        float h = h_in[i];
        g_h[i] = h;
        split1(h, g_h_hi[i], g_h_lo[i]);
    }
}

__global__ __launch_bounds__(256) void convert_x(const float* __restrict__ x)
{
    size_t i4 = (size_t)blockIdx.x * 256 + threadIdx.x;
    float4 v = *(const float4*)(x + i4 * 4);
    union { bf16 h[4]; uint2 u; } H, L;
    split1(v.x, H.h[0], L.h[0]);
    split1(v.y, H.h[1], L.h[1]);
    split1(v.z, H.h[2], L.h[2]);
    split1(v.w, H.h[3], L.h[3]);
    *(uint2*)(g_x_hi + i4 * 4) = H.u;
    *(uint2*)(g_x_lo + i4 * 4) = L.u;
}

// in: [K,N] fp32 -> out rows indexed by (interleave ? (c%1024)*4+c/1024 : c)
__global__ void transpose_split(const float* __restrict__ in, bf16* __restrict__ oh,
                                bf16* __restrict__ ol, int K, int N, int interleave)
{
    __shared__ float tile[32][33];
    const int kb = blockIdx.y * 32;
    const int nb = blockIdx.x * 32;
    const int tx = threadIdx.x;
    for (int r = threadIdx.y; r < 32; r += 8)
        tile[r][tx] = in[(size_t)(kb + r) * N + nb + tx];
    __syncthreads();
    for (int rr = threadIdx.y; rr < 32; rr += 8) {
        float v = tile[tx][rr];
        bf16 hi, lo;
        split1(v, hi, lo);
        int c = nb + rr;
        int n_new = interleave ? ((c & 1023) * 4 + (c >> 10)) : c;
        const size_t o = (size_t)n_new * K + kb + tx;
        oh[o] = hi;
        ol[o] = lo;
    }
}

__global__ void permute_bias(const float* __restrict__ b)
{
    int c = blockIdx.x * 256 + threadIdx.x;
    if (c < FOURH) g_bias[(c & 1023) * 4 + (c >> 10)] = b[c];
}

// ---------------------------------------------------------------------------
// kernel_launch
// ---------------------------------------------------------------------------
extern "C" void kernel_launch(void* const* d_in, const int* in_sizes, int n_in,
                              void* d_out, int out_size)
{
    const float* X    = (const float*)d_in[0];
    const int*   seq  = (const int*)d_in[1];
    const float* c_in = (const float*)d_in[2];
    const float* h_in = (const float*)d_in[3];
    const float* W    = (const float*)d_in[4];
    const float* bias = (const float*)d_in[5];
    const float* Wout = (const float*)d_in[6];
    const float* bout = (const float*)d_in[7];
    float* out = (float*)d_out;

    float *p_xw, *p_bias;
    bf16 *p_xh, *p_xl, *p_fh, *p_fl;
    bf16 *p_wxh, *p_wxl, *p_whh, *p_whl, *p_woh, *p_wol;
    cudaGetSymbolAddress((void**)&p_xw, g_xw);
    cudaGetSymbolAddress((void**)&p_bias, g_bias);
    cudaGetSymbolAddress((void**)&p_xh, g_x_hi);
    cudaGetSymbolAddress((void**)&p_xl, g_x_lo);
    cudaGetSymbolAddress((void**)&p_fh, g_f_hi);
    cudaGetSymbolAddress((void**)&p_fl, g_f_lo);
    cudaGetSymbolAddress((void**)&p_wxh, g_wx_hi);
    cudaGetSymbolAddress((void**)&p_wxl, g_wx_lo);
    cudaGetSymbolAddress((void**)&p_whh, g_wh_hi);
    cudaGetSymbolAddress((void**)&p_whl, g_wh_lo);
    cudaGetSymbolAddress((void**)&p_woh, g_wo_hi);
    cudaGetSymbolAddress((void**)&p_wol, g_wo_lo);

    cudaFuncSetAttribute(gemm_bf16x3, cudaFuncAttributeMaxDynamicSharedMemorySize, GEMM_SMEM);
    cudaFuncSetAttribute(lstm_step_fused, cudaFuncAttributeMaxDynamicSharedMemorySize, GEMM_SMEM);

    // prep
    init_state<<<(BB * HH + 255) / 256, 256>>>(c_in, h_in);
    convert_x<<<(int)((size_t)BT * FF / 4 / 256), 256>>>(X);
    transpose_split<<<dim3(FOURH / 32, FF / 32), dim3(32, 8)>>>(W, p_wxh, p_wxl, FF, FOURH, 1);
    transpose_split<<<dim3(FOURH / 32, HH / 32), dim3(32, 8)>>>(W + (size_t)FF * FOURH, p_whh, p_whl, HH, FOURH, 1);
    transpose_split<<<dim3(NOUT / 32, HH / 32), dim3(32, 8)>>>(Wout, p_woh, p_wol, HH, NOUT, 0);
    permute_bias<<<FOURH / 256, 256>>>(bias);

    // XW = X @ Wx^T + b (interleaved cols)
    gemm_bf16x3<<<dim3(FOURH / 128, BT / 128), 256, GEMM_SMEM>>>(
        p_xh, p_xl, p_wxh, p_wxl, p_bias, p_xw, FOURH, FF);

    // recurrence (fused GEMM + cell)
    for (int t = 0; t < TT; t++)
        lstm_step_fused<<<dim3(FOURH / 128, BB / 128), 256, GEMM_SMEM>>>(t, seq);

    // head
    gemm_bf16x3<<<dim3(NOUT / 128, BT / 128), 256, GEMM_SMEM>>>(
        p_fh, p_fl, p_woh, p_wol, bout, out, NOUT, HH);
}

// round 5
// speedup vs baseline: 3.6667x; 1.3479x over previous
#include <cuda_runtime.h>
#include <cuda_fp16.h>
#include <math.h>
#include <stdint.h>

#define BB 512
#define TT 128
#define FF 1024
#define HH 1024
#define NOUT 256
#define FOURH 4096
#define BT 65536

typedef __half h16;

// ---------------------------------------------------------------------------
// Device-global scratch
// ---------------------------------------------------------------------------
__device__ float g_xw[(size_t)BT * FOURH];     // X @ Wx + b, gate-interleaved cols
__device__ float g_c[BB * HH];
__device__ float g_h[BB * HH];
__device__ float g_bias[FOURH];                // permuted bias
__device__ h16   g_x16[(size_t)BT * FF];       // X as fp16
__device__ h16   g_f16[(size_t)BT * HH];       // masked h outputs, fp16
__device__ h16   g_h16[BB * HH];               // h state, fp16
__device__ h16   g_wx_hi[(size_t)FOURH * FF];  // Wx^T [4H,F] K-major, interleaved rows
__device__ h16   g_wx_lo[(size_t)FOURH * FF];
__device__ h16   g_wh_hi[(size_t)FOURH * HH];
__device__ h16   g_wh_lo[(size_t)FOURH * HH];
__device__ h16   g_wo_hi[NOUT * HH];
__device__ h16   g_wo_lo[NOUT * HH];

// ---------------------------------------------------------------------------
// Baseline-PTX helpers (legal on plain sm_103 target)
// ---------------------------------------------------------------------------
__device__ __forceinline__ uint32_t smem_u32(const void* p) {
    uint32_t a;
    asm("{ .reg .u64 t; cvta.to.shared.u64 t, %1; cvt.u32.u64 %0, t; }"
        : "=r"(a) : "l"(p));
    return a;
}
__device__ __forceinline__ void cp16(uint32_t dst, const void* src) {
    asm volatile("cp.async.cg.shared.global [%0], [%1], 16;"
                 :: "r"(dst), "l"(src) : "memory");
}
__device__ __forceinline__ void ldsm4(uint32_t* r, uint32_t addr) {
    asm volatile("ldmatrix.sync.aligned.m8n8.x4.shared.b16 {%0,%1,%2,%3}, [%4];"
                 : "=r"(r[0]), "=r"(r[1]), "=r"(r[2]), "=r"(r[3]) : "r"(addr));
}
__device__ __forceinline__ void mma16816(float* d, const uint32_t* a, const uint32_t* b) {
    asm volatile(
        "mma.sync.aligned.m16n8k16.row.col.f32.f16.f16.f32 "
        "{%0,%1,%2,%3}, {%4,%5,%6,%7}, {%8,%9}, {%0,%1,%2,%3};"
        : "+f"(d[0]), "+f"(d[1]), "+f"(d[2]), "+f"(d[3])
        : "r"(a[0]), "r"(a[1]), "r"(a[2]), "r"(a[3]), "r"(b[0]), "r"(b[1]));
}

// ---------------------------------------------------------------------------
// GEMM tile machinery. BM=BN=128, BK=32, 256 threads (8 warps 2x4).
// Operands per stage: A (fp16), Bh, Bl.
// ---------------------------------------------------------------------------
#define ROWB 80
#define OP_BYTES (128 * ROWB)
#define OFF_A  0
#define OFF_BH (1 * OP_BYTES)
#define OFF_BL (2 * OP_BYTES)
#define STAGE_BYTES (3 * OP_BYTES)         // 30720
#define NSTAGE 4
#define GEMM_SMEM (NSTAGE * STAGE_BYTES)   // 122880

__device__ __forceinline__ void load_stage(
    uint32_t stg, const h16* __restrict__ A,
    const h16* __restrict__ Bh, const h16* __restrict__ Bl,
    int m0, int n0, int k0, int K, int tid)
{
#pragma unroll
    for (int i = 0; i < 2; i++) {
        const int c = tid + i * 256;
        const int row = c >> 2;
        const int seg = c & 3;
        const uint32_t soff = (uint32_t)(row * ROWB + seg * 16);
        const size_t ga = (size_t)(m0 + row) * K + k0 + seg * 8;
        const size_t gb = (size_t)(n0 + row) * K + k0 + seg * 8;
        cp16(stg + OFF_A  + soff, A + ga);
        cp16(stg + OFF_BH + soff, Bh + gb);
        cp16(stg + OFF_BL + soff, Bl + gb);
    }
}

__device__ __forceinline__ void gemm_mainloop(
    uint32_t SM, const h16* __restrict__ A,
    const h16* __restrict__ Bh, const h16* __restrict__ Bl,
    int m0, int n0, int K, int tid, float acc[4][4][4])
{
    const int lane = tid & 31;
    const int wid  = tid >> 5;
    const int wm   = wid & 1;
    const int wn   = wid >> 1;
    const int NC = K >> 5;

#pragma unroll
    for (int s = 0; s < NSTAGE - 1; s++) {
        load_stage(SM + s * STAGE_BYTES, A, Bh, Bl, m0, n0, s * 32, K, tid);
        asm volatile("cp.async.commit_group;" ::: "memory");
    }

    const int arow = wm * 64 + (lane & 15);
    const uint32_t akoff = (uint32_t)((lane >> 4) * 16);
    const int bsel = lane >> 3;
    const int bn = wn * 32 + ((bsel >> 1) << 3) + (lane & 7);
    const uint32_t bkoff = (uint32_t)((bsel & 1) * 16);

    for (int it = 0; it < NC; it++) {
        asm volatile("cp.async.wait_group %0;" :: "n"(NSTAGE - 2) : "memory");
        __syncthreads();

        const int nx = it + NSTAGE - 1;
        if (nx < NC)
            load_stage(SM + (uint32_t)(nx & (NSTAGE - 1)) * STAGE_BYTES,
                       A, Bh, Bl, m0, n0, nx * 32, K, tid);
        asm volatile("cp.async.commit_group;" ::: "memory");

        const uint32_t stg = SM + (uint32_t)(it & (NSTAGE - 1)) * STAGE_BYTES;
#pragma unroll
        for (int ks = 0; ks < 2; ks++) {
            uint32_t ah[4][4], bh[4][2], bl[4][2];
            const uint32_t ak = (uint32_t)(ks * 32) + akoff;
#pragma unroll
            for (int mt = 0; mt < 4; mt++)
                ldsm4(ah[mt], stg + OFF_A + (uint32_t)((arow + mt * 16) * ROWB) + ak);
            const uint32_t bk = (uint32_t)(ks * 32) + bkoff;
#pragma unroll
            for (int np = 0; np < 2; np++) {
                const uint32_t bd = stg + (uint32_t)((bn + np * 16) * ROWB) + bk;
                uint32_t tr[4];
                ldsm4(tr, bd + OFF_BH);
                bh[2 * np][0] = tr[0]; bh[2 * np][1] = tr[1];
                bh[2 * np + 1][0] = tr[2]; bh[2 * np + 1][1] = tr[3];
                ldsm4(tr, bd + OFF_BL);
                bl[2 * np][0] = tr[0]; bl[2 * np][1] = tr[1];
                bl[2 * np + 1][0] = tr[2]; bl[2 * np + 1][1] = tr[3];
            }
#pragma unroll
            for (int mt = 0; mt < 4; mt++)
#pragma unroll
                for (int nt = 0; nt < 4; nt++) {
                    mma16816(acc[mt][nt], ah[mt], bh[nt]);
                    mma16816(acc[mt][nt], ah[mt], bl[nt]);
                }
        }
    }
}

// ---------------------------------------------------------------------------
// Plain GEMM (XW and head): C = A@B^T (+bias)
// ---------------------------------------------------------------------------
__global__ __launch_bounds__(256, 1)
void gemm_f16x2(const h16* __restrict__ A, const h16* __restrict__ Bh,
                const h16* __restrict__ Bl, const float* __restrict__ bias,
                float* __restrict__ C, int N, int K)
{
    extern __shared__ char smem_raw[];
    const uint32_t SM = smem_u32(smem_raw);
    const int tid  = threadIdx.x;
    const int lane = tid & 31;
    const int wid  = tid >> 5;
    const int wm   = wid & 1;
    const int wn   = wid >> 1;
    const int m0 = blockIdx.y * 128;
    const int n0 = blockIdx.x * 128;

    float acc[4][4][4];
#pragma unroll
    for (int a = 0; a < 4; a++)
#pragma unroll
        for (int b = 0; b < 4; b++)
#pragma unroll
            for (int cc = 0; cc < 4; cc++) acc[a][b][cc] = 0.0f;

    gemm_mainloop(SM, A, Bh, Bl, m0, n0, K, tid, acc);

    const int colq = (lane & 3) * 2;
    const int rowq = lane >> 2;
#pragma unroll
    for (int nt = 0; nt < 4; nt++) {
        const int col = n0 + wn * 32 + nt * 8 + colq;
        float bx = 0.f, by = 0.f;
        if (bias) { float2 bv = *(const float2*)(bias + col); bx = bv.x; by = bv.y; }
#pragma unroll
        for (int mt = 0; mt < 4; mt++) {
            const int r0 = m0 + wm * 64 + mt * 16 + rowq;
            *(float2*)(C + (size_t)r0 * N + col) =
                make_float2(acc[mt][nt][0] + bx, acc[mt][nt][1] + by);
            *(float2*)(C + (size_t)(r0 + 8) * N + col) =
                make_float2(acc[mt][nt][2] + bx, acc[mt][nt][3] + by);
        }
    }
}

// ---------------------------------------------------------------------------
// Fused recurrent step
// ---------------------------------------------------------------------------
__device__ __forceinline__ float sigf(float x) { return 1.0f / (1.0f + expf(-x)); }
__device__ __forceinline__ void splitw(float v, h16& hi, h16& lo) {
    hi = __float2half(v);
    lo = __float2half(v - __half2float(hi));
}

#define ZPITCH 132

__global__ __launch_bounds__(256, 1)
void lstm_step_fused(int t, const int* __restrict__ seq)
{
    extern __shared__ char smem_raw[];
    const uint32_t SM = smem_u32(smem_raw);
    float* zs = (float*)smem_raw;
    const int tid  = threadIdx.x;
    const int lane = tid & 31;
    const int wid  = tid >> 5;
    const int wm   = wid & 1;
    const int wn   = wid >> 1;
    const int m0 = blockIdx.y * 128;
    const int n0 = blockIdx.x * 128;

    float acc[4][4][4];
#pragma unroll
    for (int a = 0; a < 4; a++)
#pragma unroll
        for (int b = 0; b < 4; b++)
#pragma unroll
            for (int cc = 0; cc < 4; cc++) acc[a][b][cc] = 0.0f;

    gemm_mainloop(SM, g_h16, g_wh_hi, g_wh_lo, m0, n0, HH, tid, acc);

    __syncthreads();

    const int colq = (lane & 3) * 2;
    const int rowq = lane >> 2;
#pragma unroll
    for (int nt = 0; nt < 4; nt++) {
        const int col = wn * 32 + nt * 8 + colq;
#pragma unroll
        for (int mt = 0; mt < 4; mt++) {
            const int r0 = wm * 64 + mt * 16 + rowq;
            *(float2*)&zs[r0 * ZPITCH + col] = make_float2(acc[mt][nt][0], acc[mt][nt][1]);
            *(float2*)&zs[(r0 + 8) * ZPITCH + col] = make_float2(acc[mt][nt][2], acc[mt][nt][3]);
        }
    }
    __syncthreads();

#pragma unroll
    for (int i = 0; i < 16; i++) {
        const int idx = i * 256 + tid;
        const int r = idx >> 5;
        const int u = idx & 31;
        const int b = m0 + r;
        const int hx = (n0 >> 2) + u;

        float4 z4 = *(float4*)&zs[r * ZPITCH + 4 * u];
        float4 x4 = *(const float4*)(g_xw + ((size_t)b * TT + t) * FOURH + n0 + 4 * u);

        const float zi = z4.x + x4.x;
        const float zj = z4.y + x4.y;
        const float zf = z4.z + x4.z;
        const float zo = z4.w + x4.w;

        const size_t si = (size_t)b * HH + hx;
        const float c = g_c[si];
        const float hprev = g_h[si];
        const bool m = t < seq[b];

        const float nc = c * sigf(zf + 1.0f) + sigf(zi) * tanhf(zj);
        const float nh = tanhf(nc) * sigf(zo);

        const float co = m ? nc : c;
        const float ho = m ? nh : hprev;
        const float fe = m ? nh : 0.0f;

        g_c[si] = co;
        g_h[si] = ho;
        g_h16[si] = __float2half(ho);
        g_f16[((size_t)b * TT + t) * HH + hx] = __float2half(fe);
    }
}

// ---------------------------------------------------------------------------
// Prep kernels
// ---------------------------------------------------------------------------
__global__ void init_state(const float* __restrict__ c_in, const float* __restrict__ h_in)
{
    int i = blockIdx.x * blockDim.x + threadIdx.x;
    if (i < BB * HH) {
        g_c[i] = c_in[i];
        float h = h_in[i];
        g_h[i] = h;
        g_h16[i] = __float2half(h);
    }
}

__global__ __launch_bounds__(256) void convert_x(const float* __restrict__ x)
{
    size_t i4 = (size_t)blockIdx.x * 256 + threadIdx.x;
    float4 v = *(const float4*)(x + i4 * 4);
    union { h16 h[4]; uint2 u; } H;
    H.h[0] = __float2half(v.x);
    H.h[1] = __float2half(v.y);
    H.h[2] = __float2half(v.z);
    H.h[3] = __float2half(v.w);
    *(uint2*)(g_x16 + i4 * 4) = H.u;
}

// in: [K,N] fp32 -> out rows indexed by (interleave ? (c%1024)*4+c/1024 : c)
__global__ void transpose_split(const float* __restrict__ in, h16* __restrict__ oh,
                                h16* __restrict__ ol, int K, int N, int interleave)
{
    __shared__ float tile[32][33];
    const int kb = blockIdx.y * 32;
    const int nb = blockIdx.x * 32;
    const int tx = threadIdx.x;
    for (int r = threadIdx.y; r < 32; r += 8)
        tile[r][tx] = in[(size_t)(kb + r) * N + nb + tx];
    __syncthreads();
    for (int rr = threadIdx.y; rr < 32; rr += 8) {
        float v = tile[tx][rr];
        h16 hi, lo;
        splitw(v, hi, lo);
        int c = nb + rr;
        int n_new = interleave ? ((c & 1023) * 4 + (c >> 10)) : c;
        const size_t o = (size_t)n_new * K + kb + tx;
        oh[o] = hi;
        ol[o] = lo;
    }
}

__global__ void permute_bias(const float* __restrict__ b)
{
    int c = blockIdx.x * 256 + threadIdx.x;
    if (c < FOURH) g_bias[(c & 1023) * 4 + (c >> 10)] = b[c];
}

// ---------------------------------------------------------------------------
// kernel_launch
// ---------------------------------------------------------------------------
extern "C" void kernel_launch(void* const* d_in, const int* in_sizes, int n_in,
                              void* d_out, int out_size)
{
    const float* X    = (const float*)d_in[0];
    const int*   seq  = (const int*)d_in[1];
    const float* c_in = (const float*)d_in[2];
    const float* h_in = (const float*)d_in[3];
    const float* W    = (const float*)d_in[4];
    const float* bias = (const float*)d_in[5];
    const float* Wout = (const float*)d_in[6];
    const float* bout = (const float*)d_in[7];
    float* out = (float*)d_out;

    float *p_xw, *p_bias;
    h16 *p_x16, *p_f16;
    h16 *p_wxh, *p_wxl, *p_whh, *p_whl, *p_woh, *p_wol;
    cudaGetSymbolAddress((void**)&p_xw, g_xw);
    cudaGetSymbolAddress((void**)&p_bias, g_bias);
    cudaGetSymbolAddress((void**)&p_x16, g_x16);
    cudaGetSymbolAddress((void**)&p_f16, g_f16);
    cudaGetSymbolAddress((void**)&p_wxh, g_wx_hi);
    cudaGetSymbolAddress((void**)&p_wxl, g_wx_lo);
    cudaGetSymbolAddress((void**)&p_whh, g_wh_hi);
    cudaGetSymbolAddress((void**)&p_whl, g_wh_lo);
    cudaGetSymbolAddress((void**)&p_woh, g_wo_hi);
    cudaGetSymbolAddress((void**)&p_wol, g_wo_lo);

    cudaFuncSetAttribute(gemm_f16x2, cudaFuncAttributeMaxDynamicSharedMemorySize, GEMM_SMEM);
    cudaFuncSetAttribute(lstm_step_fused, cudaFuncAttributeMaxDynamicSharedMemorySize, GEMM_SMEM);

    // prep
    init_state<<<(BB * HH + 255) / 256, 256>>>(c_in, h_in);
    convert_x<<<(int)((size_t)BT * FF / 4 / 256), 256>>>(X);
    transpose_split<<<dim3(FOURH / 32, FF / 32), dim3(32, 8)>>>(W, p_wxh, p_wxl, FF, FOURH, 1);
    transpose_split<<<dim3(FOURH / 32, HH / 32), dim3(32, 8)>>>(W + (size_t)FF * FOURH, p_whh, p_whl, HH, FOURH, 1);
    transpose_split<<<dim3(NOUT / 32, HH / 32), dim3(32, 8)>>>(Wout, p_woh, p_wol, HH, NOUT, 0);
    permute_bias<<<FOURH / 256, 256>>>(bias);

    // XW = X @ Wx^T + b (interleaved cols)
    gemm_f16x2<<<dim3(FOURH / 128, BT / 128), 256, GEMM_SMEM>>>(
        p_x16, p_wxh, p_wxl, p_bias, p_xw, FOURH, FF);

    // recurrence (fused GEMM + cell)
    for (int t = 0; t < TT; t++)
        lstm_step_fused<<<dim3(FOURH / 128, BB / 128), 256, GEMM_SMEM>>>(t, seq);

    // head
    gemm_f16x2<<<dim3(NOUT / 128, BT / 128), 256, GEMM_SMEM>>>(
        p_f16, p_woh, p_wol, bout, out, NOUT, HH);
}

// round 7
// speedup vs baseline: 4.0610x; 1.1075x over previous
#include <cuda_runtime.h>
#include <cuda_fp16.h>
#include <math.h>
#include <stdint.h>

#define BB 512
#define TT 128
#define FF 1024
#define HH 1024
#define NOUT 256
#define FOURH 4096
#define BT 65536

typedef __half h16;

// ---------------------------------------------------------------------------
// Device-global scratch
// ---------------------------------------------------------------------------
__device__ float g_xw[(size_t)BT * FOURH];     // X @ Wx + b, gate-interleaved cols
__device__ float g_c[BB * HH];
__device__ float g_h[BB * HH];
__device__ float g_bias[FOURH];                // permuted bias
__device__ h16   g_x16[(size_t)BT * FF];       // X as fp16
__device__ h16   g_f16[(size_t)BT * HH];       // masked h outputs, fp16
__device__ h16   g_h16[2][BB * HH];            // DOUBLE-BUFFERED h state, fp16
__device__ h16   g_wx_hi[(size_t)FOURH * FF];  // Wx^T [4H,F] K-major, interleaved rows
__device__ h16   g_wx_lo[(size_t)FOURH * FF];
__device__ h16   g_wh_hi[(size_t)FOURH * HH];
__device__ h16   g_wh_lo[(size_t)FOURH * HH];
__device__ h16   g_wo_hi[NOUT * HH];
__device__ h16   g_wo_lo[NOUT * HH];

// ---------------------------------------------------------------------------
// Baseline-PTX helpers (legal on plain sm_103 target)
// ---------------------------------------------------------------------------
__device__ __forceinline__ uint32_t smem_u32(const void* p) {
    uint32_t a;
    asm("{ .reg .u64 t; cvta.to.shared.u64 t, %1; cvt.u32.u64 %0, t; }"
        : "=r"(a) : "l"(p));
    return a;
}
__device__ __forceinline__ void cp16(uint32_t dst, const void* src) {
    asm volatile("cp.async.cg.shared.global [%0], [%1], 16;"
                 :: "r"(dst), "l"(src) : "memory");
}
__device__ __forceinline__ void ldsm4(uint32_t* r, uint32_t addr) {
    asm volatile("ldmatrix.sync.aligned.m8n8.x4.shared.b16 {%0,%1,%2,%3}, [%4];"
                 : "=r"(r[0]), "=r"(r[1]), "=r"(r[2]), "=r"(r[3]) : "r"(addr));
}
__device__ __forceinline__ void mma16816(float* d, const uint32_t* a, const uint32_t* b) {
    asm volatile(
        "mma.sync.aligned.m16n8k16.row.col.f32.f16.f16.f32 "
        "{%0,%1,%2,%3}, {%4,%5,%6,%7}, {%8,%9}, {%0,%1,%2,%3};"
        : "+f"(d[0]), "+f"(d[1]), "+f"(d[2]), "+f"(d[3])
        : "r"(a[0]), "r"(a[1]), "r"(a[2]), "r"(a[3]), "r"(b[0]), "r"(b[1]));
}

// ---------------------------------------------------------------------------
// GEMM tile machinery. BN=128, BK=32, 256 threads (8 warps 2x4).
// BM = MT*32 (MT=4 -> 128, MT=2 -> 64). Stage operands: A, Bh, Bl.
// ---------------------------------------------------------------------------
#define ROWB 80
#define OP_BYTES (128 * ROWB)
#define OFF_A  0
#define OFF_BH (1 * OP_BYTES)
#define OFF_BL (2 * OP_BYTES)
#define STAGE_BYTES (3 * OP_BYTES)         // 30720
#define NSTAGE 3
#define GEMM_SMEM (NSTAGE * STAGE_BYTES)   // 92160

template <int MT>
__device__ __forceinline__ void load_stage(
    uint32_t stg, const h16* __restrict__ A,
    const h16* __restrict__ Bh, const h16* __restrict__ Bl,
    int m0, int n0, int k0, int K, int tid)
{
    constexpr int BM = MT * 32;
    // A: BM rows x 4 segs
#pragma unroll
    for (int i = 0; i < BM * 4 / 256; i++) {
        const int c = tid + i * 256;
        const int row = c >> 2;
        const int seg = c & 3;
        cp16(stg + OFF_A + (uint32_t)(row * ROWB + seg * 16),
             A + (size_t)(m0 + row) * K + k0 + seg * 8);
    }
    // B: 128 rows x 4 segs
#pragma unroll
    for (int i = 0; i < 2; i++) {
        const int c = tid + i * 256;
        const int row = c >> 2;
        const int seg = c & 3;
        const uint32_t soff = (uint32_t)(row * ROWB + seg * 16);
        const size_t gb = (size_t)(n0 + row) * K + k0 + seg * 8;
        cp16(stg + OFF_BH + soff, Bh + gb);
        cp16(stg + OFF_BL + soff, Bl + gb);
    }
}

template <int MT>
__device__ __forceinline__ void gemm_mainloop(
    uint32_t SM, const h16* __restrict__ A,
    const h16* __restrict__ Bh, const h16* __restrict__ Bl,
    int m0, int n0, int K, int tid, float acc[MT][4][4])
{
    const int lane = tid & 31;
    const int wid  = tid >> 5;
    const int wm   = wid & 1;
    const int wn   = wid >> 1;
    const int NC = K >> 5;

#pragma unroll
    for (int s = 0; s < NSTAGE - 1; s++) {
        load_stage<MT>(SM + s * STAGE_BYTES, A, Bh, Bl, m0, n0, s * 32, K, tid);
        asm volatile("cp.async.commit_group;" ::: "memory");
    }

    const int arow = wm * (MT * 16) + (lane & 15);
    const uint32_t akoff = (uint32_t)((lane >> 4) * 16);
    const int bsel = lane >> 3;
    const int bn = wn * 32 + ((bsel >> 1) << 3) + (lane & 7);
    const uint32_t bkoff = (uint32_t)((bsel & 1) * 16);

    for (int it = 0; it < NC; it++) {
        asm volatile("cp.async.wait_group %0;" :: "n"(NSTAGE - 2) : "memory");
        __syncthreads();

        const int nx = it + NSTAGE - 1;
        if (nx < NC)
            load_stage<MT>(SM + (uint32_t)((nx % NSTAGE)) * STAGE_BYTES,
                           A, Bh, Bl, m0, n0, nx * 32, K, tid);
        asm volatile("cp.async.commit_group;" ::: "memory");

        const uint32_t stg = SM + (uint32_t)(it % NSTAGE) * STAGE_BYTES;
#pragma unroll
        for (int ks = 0; ks < 2; ks++) {
            uint32_t ah[MT][4], bh[4][2], bl[4][2];
            const uint32_t ak = (uint32_t)(ks * 32) + akoff;
#pragma unroll
            for (int mt = 0; mt < MT; mt++)
                ldsm4(ah[mt], stg + OFF_A + (uint32_t)((arow + mt * 16) * ROWB) + ak);
            const uint32_t bk = (uint32_t)(ks * 32) + bkoff;
#pragma unroll
            for (int np = 0; np < 2; np++) {
                const uint32_t bd = stg + (uint32_t)((bn + np * 16) * ROWB) + bk;
                uint32_t tr[4];
                ldsm4(tr, bd + OFF_BH);
                bh[2 * np][0] = tr[0]; bh[2 * np][1] = tr[1];
                bh[2 * np + 1][0] = tr[2]; bh[2 * np + 1][1] = tr[3];
                ldsm4(tr, bd + OFF_BL);
                bl[2 * np][0] = tr[0]; bl[2 * np][1] = tr[1];
                bl[2 * np + 1][0] = tr[2]; bl[2 * np + 1][1] = tr[3];
            }
#pragma unroll
            for (int mt = 0; mt < MT; mt++)
#pragma unroll
                for (int nt = 0; nt < 4; nt++) {
                    mma16816(acc[mt][nt], ah[mt], bh[nt]);
                    mma16816(acc[mt][nt], ah[mt], bl[nt]);
                }
        }
    }
}

// ---------------------------------------------------------------------------
// Plain GEMM (XW and head): C = A@B^T (+bias). BM=128.
// ---------------------------------------------------------------------------
__global__ __launch_bounds__(256, 2)
void gemm_f16x2(const h16* __restrict__ A, const h16* __restrict__ Bh,
                const h16* __restrict__ Bl, const float* __restrict__ bias,
                float* __restrict__ C, int N, int K)
{
    extern __shared__ char smem_raw[];
    const uint32_t SM = smem_u32(smem_raw);
    const int tid  = threadIdx.x;
    const int lane = tid & 31;
    const int wid  = tid >> 5;
    const int wm   = wid & 1;
    const int wn   = wid >> 1;
    const int m0 = blockIdx.y * 128;
    const int n0 = blockIdx.x * 128;

    float acc[4][4][4];
#pragma unroll
    for (int a = 0; a < 4; a++)
#pragma unroll
        for (int b = 0; b < 4; b++)
#pragma unroll
            for (int cc = 0; cc < 4; cc++) acc[a][b][cc] = 0.0f;

    gemm_mainloop<4>(SM, A, Bh, Bl, m0, n0, K, tid, acc);

    const int colq = (lane & 3) * 2;
    const int rowq = lane >> 2;
#pragma unroll
    for (int nt = 0; nt < 4; nt++) {
        const int col = n0 + wn * 32 + nt * 8 + colq;
        float bx = 0.f, by = 0.f;
        if (bias) { float2 bv = *(const float2*)(bias + col); bx = bv.x; by = bv.y; }
#pragma unroll
        for (int mt = 0; mt < 4; mt++) {
            const int r0 = m0 + wm * 64 + mt * 16 + rowq;
            *(float2*)(C + (size_t)r0 * N + col) =
                make_float2(acc[mt][nt][0] + bx, acc[mt][nt][1] + by);
            *(float2*)(C + (size_t)(r0 + 8) * N + col) =
                make_float2(acc[mt][nt][2] + bx, acc[mt][nt][3] + by);
        }
    }
}

// ---------------------------------------------------------------------------
// Fused recurrent step: BM=64 tiles (grid 32 x 8 = 256 CTAs).
// Reads h from g_h16[t&1], writes new h to g_h16[(t+1)&1]  (no cross-CTA race).
// ---------------------------------------------------------------------------
__device__ __forceinline__ float sigf(float x) { return 1.0f / (1.0f + expf(-x)); }
__device__ __forceinline__ void splitw(float v, h16& hi, h16& lo) {
    hi = __float2half(v);
    lo = __float2half(v - __half2float(hi));
}

#define ZPITCH 132

__global__ __launch_bounds__(256, 2)
void lstm_step_fused(int t, const int* __restrict__ seq)
{
    extern __shared__ char smem_raw[];
    const uint32_t SM = smem_u32(smem_raw);
    float* zs = (float*)smem_raw;
    const int tid  = threadIdx.x;
    const int lane = tid & 31;
    const int wid  = tid >> 5;
    const int wm   = wid & 1;
    const int wn   = wid >> 1;
    const int m0 = blockIdx.y * 64;        // batch offset (BM=64)
    const int n0 = blockIdx.x * 128;       // interleaved gate-col offset

    const h16* __restrict__ h_rd = g_h16[t & 1];
    h16* __restrict__ h_wr = g_h16[(t + 1) & 1];

    float acc[2][4][4];
#pragma unroll
    for (int a = 0; a < 2; a++)
#pragma unroll
        for (int b = 0; b < 4; b++)
#pragma unroll
            for (int cc = 0; cc < 4; cc++) acc[a][b][cc] = 0.0f;

    gemm_mainloop<2>(SM, h_rd, g_wh_hi, g_wh_lo, m0, n0, HH, tid, acc);

    __syncthreads();

    // acc -> smem z tile (64 x 128)
    const int colq = (lane & 3) * 2;
    const int rowq = lane >> 2;
#pragma unroll
    for (int nt = 0; nt < 4; nt++) {
        const int col = wn * 32 + nt * 8 + colq;
#pragma unroll
        for (int mt = 0; mt < 2; mt++) {
            const int r0 = wm * 32 + mt * 16 + rowq;
            *(float2*)&zs[r0 * ZPITCH + col] = make_float2(acc[mt][nt][0], acc[mt][nt][1]);
            *(float2*)&zs[(r0 + 8) * ZPITCH + col] = make_float2(acc[mt][nt][2], acc[mt][nt][3]);
        }
    }
    __syncthreads();

    // cell epilogue: 64 rows x 32 units
#pragma unroll
    for (int i = 0; i < 8; i++) {
        const int idx = i * 256 + tid;
        const int r = idx >> 5;
        const int u = idx & 31;
        const int b = m0 + r;
        const int hx = (n0 >> 2) + u;

        float4 z4 = *(float4*)&zs[r * ZPITCH + 4 * u];
        float4 x4 = *(const float4*)(g_xw + ((size_t)b * TT + t) * FOURH + n0 + 4 * u);

        const float zi = z4.x + x4.x;
        const float zj = z4.y + x4.y;
        const float zf = z4.z + x4.z;
        const float zo = z4.w + x4.w;

        const size_t si = (size_t)b * HH + hx;
        const float c = g_c[si];
        const float hprev = g_h[si];
        const bool m = t < seq[b];

        const float nc = c * sigf(zf + 1.0f) + sigf(zi) * tanhf(zj);
        const float nh = tanhf(nc) * sigf(zo);

        const float co = m ? nc : c;
        const float ho = m ? nh : hprev;
        const float fe = m ? nh : 0.0f;

        g_c[si] = co;
        g_h[si] = ho;
        h_wr[si] = __float2half(ho);
        g_f16[((size_t)b * TT + t) * HH + hx] = __float2half(fe);
    }
}

// ---------------------------------------------------------------------------
// Prep kernels
// ---------------------------------------------------------------------------
__global__ void init_state(const float* __restrict__ c_in, const float* __restrict__ h_in)
{
    int i = blockIdx.x * blockDim.x + threadIdx.x;
    if (i < BB * HH) {
        g_c[i] = c_in[i];
        float h = h_in[i];
        g_h[i] = h;
        g_h16[0][i] = __float2half(h);
    }
}

__global__ __launch_bounds__(256) void convert_x(const float* __restrict__ x)
{
    size_t i4 = (size_t)blockIdx.x * 256 + threadIdx.x;
    float4 v = *(const float4*)(x + i4 * 4);
    union { h16 h[4]; uint2 u; } H;
    H.h[0] = __float2half(v.x);
    H.h[1] = __float2half(v.y);
    H.h[2] = __float2half(v.z);
    H.h[3] = __float2half(v.w);
    *(uint2*)(g_x16 + i4 * 4) = H.u;
}

// in: [K,N] fp32 -> out rows indexed by (interleave ? (c%1024)*4+c/1024 : c)
__global__ void transpose_split(const float* __restrict__ in, h16* __restrict__ oh,
                                h16* __restrict__ ol, int K, int N, int interleave)
{
    __shared__ float tile[32][33];
    const int kb = blockIdx.y * 32;
    const int nb = blockIdx.x * 32;
    const int tx = threadIdx.x;
    for (int r = threadIdx.y; r < 32; r += 8)
        tile[r][tx] = in[(size_t)(kb + r) * N + nb + tx];
    __syncthreads();
    for (int rr = threadIdx.y; rr < 32; rr += 8) {
        float v = tile[tx][rr];
        h16 hi, lo;
        splitw(v, hi, lo);
        int c = nb + rr;
        int n_new = interleave ? ((c & 1023) * 4 + (c >> 10)) : c;
        const size_t o = (size_t)n_new * K + kb + tx;
        oh[o] = hi;
        ol[o] = lo;
    }
}

__global__ void permute_bias(const float* __restrict__ b)
{
    int c = blockIdx.x * 256 + threadIdx.x;
    if (c < FOURH) g_bias[(c & 1023) * 4 + (c >> 10)] = b[c];
}

// ---------------------------------------------------------------------------
// kernel_launch
// ---------------------------------------------------------------------------
extern "C" void kernel_launch(void* const* d_in, const int* in_sizes, int n_in,
                              void* d_out, int out_size)
{
    const float* X    = (const float*)d_in[0];
    const int*   seq  = (const int*)d_in[1];
    const float* c_in = (const float*)d_in[2];
    const float* h_in = (const float*)d_in[3];
    const float* W    = (const float*)d_in[4];
    const float* bias = (const float*)d_in[5];
    const float* Wout = (const float*)d_in[6];
    const float* bout = (const float*)d_in[7];
    float* out = (float*)d_out;

    float *p_xw, *p_bias;
    h16 *p_x16, *p_f16;
    h16 *p_wxh, *p_wxl, *p_whh, *p_whl, *p_woh, *p_wol;
    cudaGetSymbolAddress((void**)&p_xw, g_xw);
    cudaGetSymbolAddress((void**)&p_bias, g_bias);
    cudaGetSymbolAddress((void**)&p_x16, g_x16);
    cudaGetSymbolAddress((void**)&p_f16, g_f16);
    cudaGetSymbolAddress((void**)&p_wxh, g_wx_hi);
    cudaGetSymbolAddress((void**)&p_wxl, g_wx_lo);
    cudaGetSymbolAddress((void**)&p_whh, g_wh_hi);
    cudaGetSymbolAddress((void**)&p_whl, g_wh_lo);
    cudaGetSymbolAddress((void**)&p_woh, g_wo_hi);
    cudaGetSymbolAddress((void**)&p_wol, g_wo_lo);

    cudaFuncSetAttribute(gemm_f16x2, cudaFuncAttributeMaxDynamicSharedMemorySize, GEMM_SMEM);
    cudaFuncSetAttribute(lstm_step_fused, cudaFuncAttributeMaxDynamicSharedMemorySize, GEMM_SMEM);

    // prep
    init_state<<<(BB * HH + 255) / 256, 256>>>(c_in, h_in);
    convert_x<<<(int)((size_t)BT * FF / 4 / 256), 256>>>(X);
    transpose_split<<<dim3(FOURH / 32, FF / 32), dim3(32, 8)>>>(W, p_wxh, p_wxl, FF, FOURH, 1);
    transpose_split<<<dim3(FOURH / 32, HH / 32), dim3(32, 8)>>>(W + (size_t)FF * FOURH, p_whh, p_whl, HH, FOURH, 1);
    transpose_split<<<dim3(NOUT / 32, HH / 32), dim3(32, 8)>>>(Wout, p_woh, p_wol, HH, NOUT, 0);
    permute_bias<<<FOURH / 256, 256>>>(bias);

    // XW = X @ Wx^T + b (interleaved cols)
    gemm_f16x2<<<dim3(FOURH / 128, BT / 128), 256, GEMM_SMEM>>>(
        p_x16, p_wxh, p_wxl, p_bias, p_xw, FOURH, FF);

    // recurrence (fused GEMM + cell), BM=64 tiles, double-buffered h
    for (int t = 0; t < TT; t++)
        lstm_step_fused<<<dim3(FOURH / 128, BB / 64), 256, GEMM_SMEM>>>(t, seq);

    // head
    gemm_f16x2<<<dim3(NOUT / 128, BT / 128), 256, GEMM_SMEM>>>(
        p_f16, p_woh, p_wol, bout, out, NOUT, HH);
}

// round 8
// speedup vs baseline: 4.7290x; 1.1645x over previous
#include <cuda_runtime.h>
#include <cuda_fp16.h>
#include <math.h>
#include <stdint.h>

#define BB 512
#define TT 128
#define FF 1024
#define HH 1024
#define NOUT 256
#define FOURH 4096
#define BT 65536

typedef __half h16;

// ---------------------------------------------------------------------------
// Device-global scratch
// ---------------------------------------------------------------------------
__device__ float g_xw[(size_t)BT * FOURH];     // X @ Wx + b, gate-interleaved cols
__device__ float g_c[BB * HH];
__device__ float g_h[BB * HH];
__device__ float g_bias[FOURH];                // permuted bias
__device__ h16   g_x16[(size_t)BT * FF];       // X as fp16
__device__ h16   g_f16[(size_t)BT * HH];       // masked h outputs, fp16
__device__ h16   g_h16[2][BB * HH];            // double-buffered h state, fp16
__device__ h16   g_wx_hi[(size_t)FOURH * FF];  // Wx^T [4H,F] K-major, interleaved rows
__device__ h16   g_wh_hi[(size_t)FOURH * HH];
__device__ h16   g_wh_lo[(size_t)FOURH * HH];
__device__ h16   g_wo_hi[NOUT * HH];

// ---------------------------------------------------------------------------
// Baseline-PTX helpers (legal on plain sm_103 target)
// ---------------------------------------------------------------------------
__device__ __forceinline__ uint32_t smem_u32(const void* p) {
    uint32_t a;
    asm("{ .reg .u64 t; cvta.to.shared.u64 t, %1; cvt.u32.u64 %0, t; }"
        : "=r"(a) : "l"(p));
    return a;
}
__device__ __forceinline__ void cp16(uint32_t dst, const void* src) {
    asm volatile("cp.async.cg.shared.global [%0], [%1], 16;"
                 :: "r"(dst), "l"(src) : "memory");
}
__device__ __forceinline__ void ldsm4(uint32_t* r, uint32_t addr) {
    asm volatile("ldmatrix.sync.aligned.m8n8.x4.shared.b16 {%0,%1,%2,%3}, [%4];"
                 : "=r"(r[0]), "=r"(r[1]), "=r"(r[2]), "=r"(r[3]) : "r"(addr));
}
__device__ __forceinline__ void mma16816(float* d, const uint32_t* a, const uint32_t* b) {
    asm volatile(
        "mma.sync.aligned.m16n8k16.row.col.f32.f16.f16.f32 "
        "{%0,%1,%2,%3}, {%4,%5,%6,%7}, {%8,%9}, {%0,%1,%2,%3};"
        : "+f"(d[0]), "+f"(d[1]), "+f"(d[2]), "+f"(d[3])
        : "r"(a[0]), "r"(a[1]), "r"(a[2]), "r"(a[3]), "r"(b[0]), "r"(b[1]));
}

// ---------------------------------------------------------------------------
// GEMM tile machinery. BN=128, BK=32, 256 threads (8 warps 2x4).
// BM = MT*32. NB = number of B terms (1 or 2). NST = pipeline stages.
// ---------------------------------------------------------------------------
#define ROWB 80
#define OP_BYTES (128 * ROWB)              // 10240

template <int MT, int NB, int NST>
__device__ __forceinline__ void load_stage(
    uint32_t stg, const h16* __restrict__ A,
    const h16* __restrict__ Bh, const h16* __restrict__ Bl,
    int m0, int n0, int k0, int K, int tid)
{
    constexpr int BM = MT * 32;
#pragma unroll
    for (int i = 0; i < BM * 4 / 256; i++) {
        const int c = tid + i * 256;
        const int row = c >> 2;
        const int seg = c & 3;
        cp16(stg + (uint32_t)(row * ROWB + seg * 16),
             A + (size_t)(m0 + row) * K + k0 + seg * 8);
    }
#pragma unroll
    for (int i = 0; i < 2; i++) {
        const int c = tid + i * 256;
        const int row = c >> 2;
        const int seg = c & 3;
        const uint32_t soff = (uint32_t)(row * ROWB + seg * 16);
        const size_t gb = (size_t)(n0 + row) * K + k0 + seg * 8;
        cp16(stg + OP_BYTES + soff, Bh + gb);
        if (NB == 2) cp16(stg + 2 * OP_BYTES + soff, Bl + gb);
    }
}

template <int MT, int NB, int NST>
__device__ __forceinline__ void gemm_mainloop(
    uint32_t SM, const h16* __restrict__ A,
    const h16* __restrict__ Bh, const h16* __restrict__ Bl,
    int m0, int n0, int K, int tid, float acc[MT][4][4])
{
    constexpr uint32_t STG_B = (1 + NB) * OP_BYTES;
    const int lane = tid & 31;
    const int wid  = tid >> 5;
    const int wm   = wid & 1;
    const int wn   = wid >> 1;
    const int NC = K >> 5;

#pragma unroll
    for (int s = 0; s < NST - 1; s++) {
        load_stage<MT, NB, NST>(SM + s * STG_B, A, Bh, Bl, m0, n0, s * 32, K, tid);
        asm volatile("cp.async.commit_group;" ::: "memory");
    }

    const int arow = wm * (MT * 16) + (lane & 15);
    const uint32_t akoff = (uint32_t)((lane >> 4) * 16);
    const int bsel = lane >> 3;
    const int bn = wn * 32 + ((bsel >> 1) << 3) + (lane & 7);
    const uint32_t bkoff = (uint32_t)((bsel & 1) * 16);

    for (int it = 0; it < NC; it++) {
        asm volatile("cp.async.wait_group %0;" :: "n"(NST - 2) : "memory");
        __syncthreads();

        const int nx = it + NST - 1;
        if (nx < NC)
            load_stage<MT, NB, NST>(SM + (uint32_t)(nx % NST) * STG_B,
                                    A, Bh, Bl, m0, n0, nx * 32, K, tid);
        asm volatile("cp.async.commit_group;" ::: "memory");

        const uint32_t stg = SM + (uint32_t)(it % NST) * STG_B;
#pragma unroll
        for (int ks = 0; ks < 2; ks++) {
            uint32_t ah[MT][4], bh[4][2], bl[4][2];
            const uint32_t ak = (uint32_t)(ks * 32) + akoff;
#pragma unroll
            for (int mt = 0; mt < MT; mt++)
                ldsm4(ah[mt], stg + (uint32_t)((arow + mt * 16) * ROWB) + ak);
            const uint32_t bk = (uint32_t)(ks * 32) + bkoff;
#pragma unroll
            for (int np = 0; np < 2; np++) {
                const uint32_t bd = stg + (uint32_t)((bn + np * 16) * ROWB) + bk;
                uint32_t tr[4];
                ldsm4(tr, bd + OP_BYTES);
                bh[2 * np][0] = tr[0]; bh[2 * np][1] = tr[1];
                bh[2 * np + 1][0] = tr[2]; bh[2 * np + 1][1] = tr[3];
                if (NB == 2) {
                    ldsm4(tr, bd + 2 * OP_BYTES);
                    bl[2 * np][0] = tr[0]; bl[2 * np][1] = tr[1];
                    bl[2 * np + 1][0] = tr[2]; bl[2 * np + 1][1] = tr[3];
                }
            }
#pragma unroll
            for (int mt = 0; mt < MT; mt++)
#pragma unroll
                for (int nt = 0; nt < 4; nt++) {
                    mma16816(acc[mt][nt], ah[mt], bh[nt]);
                    if (NB == 2) mma16816(acc[mt][nt], ah[mt], bl[nt]);
                }
        }
    }
}

// ---------------------------------------------------------------------------
// Single-term fp16 GEMM (XW and head): C = A@B^T (+bias). BM=128, 4 stages.
// ---------------------------------------------------------------------------
#define SMEM_X1 (4 * 2 * OP_BYTES)        // 81920
__global__ __launch_bounds__(256, 2)
void gemm_f16x1(const h16* __restrict__ A, const h16* __restrict__ Bh,
                const float* __restrict__ bias, float* __restrict__ C,
                int N, int K)
{
    extern __shared__ char smem_raw[];
    const uint32_t SM = smem_u32(smem_raw);
    const int tid  = threadIdx.x;
    const int lane = tid & 31;
    const int wid  = tid >> 5;
    const int wm   = wid & 1;
    const int wn   = wid >> 1;
    const int m0 = blockIdx.y * 128;
    const int n0 = blockIdx.x * 128;

    float acc[4][4][4];
#pragma unroll
    for (int a = 0; a < 4; a++)
#pragma unroll
        for (int b = 0; b < 4; b++)
#pragma unroll
            for (int cc = 0; cc < 4; cc++) acc[a][b][cc] = 0.0f;

    gemm_mainloop<4, 1, 4>(SM, A, Bh, nullptr, m0, n0, K, tid, acc);

    const int colq = (lane & 3) * 2;
    const int rowq = lane >> 2;
#pragma unroll
    for (int nt = 0; nt < 4; nt++) {
        const int col = n0 + wn * 32 + nt * 8 + colq;
        float bx = 0.f, by = 0.f;
        if (bias) { float2 bv = *(const float2*)(bias + col); bx = bv.x; by = bv.y; }
#pragma unroll
        for (int mt = 0; mt < 4; mt++) {
            const int r0 = m0 + wm * 64 + mt * 16 + rowq;
            *(float2*)(C + (size_t)r0 * N + col) =
                make_float2(acc[mt][nt][0] + bx, acc[mt][nt][1] + by);
            *(float2*)(C + (size_t)(r0 + 8) * N + col) =
                make_float2(acc[mt][nt][2] + bx, acc[mt][nt][3] + by);
        }
    }
}

// ---------------------------------------------------------------------------
// Fused recurrent step: BM=64 tiles, 2-term weights, 3 stages.
// Reads h from g_h16[t&1], writes to g_h16[(t+1)&1].
// ---------------------------------------------------------------------------
#define SMEM_REC (3 * 3 * OP_BYTES)       // 92160
__device__ __forceinline__ float sigf(float x) { return 1.0f / (1.0f + expf(-x)); }
__device__ __forceinline__ void splitw(float v, h16& hi, h16& lo) {
    hi = __float2half(v);
    lo = __float2half(v - __half2float(hi));
}

#define ZPITCH 132

__global__ __launch_bounds__(256, 2)
void lstm_step_fused(int t, const int* __restrict__ seq)
{
    extern __shared__ char smem_raw[];
    const uint32_t SM = smem_u32(smem_raw);
    float* zs = (float*)smem_raw;
    const int tid  = threadIdx.x;
    const int lane = tid & 31;
    const int wid  = tid >> 5;
    const int wm   = wid & 1;
    const int wn   = wid >> 1;
    const int m0 = blockIdx.y * 64;
    const int n0 = blockIdx.x * 128;

    const h16* __restrict__ h_rd = g_h16[t & 1];
    h16* __restrict__ h_wr = g_h16[(t + 1) & 1];

    float acc[2][4][4];
#pragma unroll
    for (int a = 0; a < 2; a++)
#pragma unroll
        for (int b = 0; b < 4; b++)
#pragma unroll
            for (int cc = 0; cc < 4; cc++) acc[a][b][cc] = 0.0f;

    gemm_mainloop<2, 2, 3>(SM, h_rd, g_wh_hi, g_wh_lo, m0, n0, HH, tid, acc);

    __syncthreads();

    const int colq = (lane & 3) * 2;
    const int rowq = lane >> 2;
#pragma unroll
    for (int nt = 0; nt < 4; nt++) {
        const int col = wn * 32 + nt * 8 + colq;
#pragma unroll
        for (int mt = 0; mt < 2; mt++) {
            const int r0 = wm * 32 + mt * 16 + rowq;
            *(float2*)&zs[r0 * ZPITCH + col] = make_float2(acc[mt][nt][0], acc[mt][nt][1]);
            *(float2*)&zs[(r0 + 8) * ZPITCH + col] = make_float2(acc[mt][nt][2], acc[mt][nt][3]);
        }
    }
    __syncthreads();

#pragma unroll
    for (int i = 0; i < 8; i++) {
        const int idx = i * 256 + tid;
        const int r = idx >> 5;
        const int u = idx & 31;
        const int b = m0 + r;
        const int hx = (n0 >> 2) + u;

        float4 z4 = *(float4*)&zs[r * ZPITCH + 4 * u];
        float4 x4 = *(const float4*)(g_xw + ((size_t)b * TT + t) * FOURH + n0 + 4 * u);

        const float zi = z4.x + x4.x;
        const float zj = z4.y + x4.y;
        const float zf = z4.z + x4.z;
        const float zo = z4.w + x4.w;

        const size_t si = (size_t)b * HH + hx;
        const float c = g_c[si];
        const float hprev = g_h[si];
        const bool m = t < seq[b];

        const float nc = c * sigf(zf + 1.0f) + sigf(zi) * tanhf(zj);
        const float nh = tanhf(nc) * sigf(zo);

        const float co = m ? nc : c;
        const float ho = m ? nh : hprev;
        const float fe = m ? nh : 0.0f;

        g_c[si] = co;
        g_h[si] = ho;
        h_wr[si] = __float2half(ho);
        g_f16[((size_t)b * TT + t) * HH + hx] = __float2half(fe);
    }
}

// ---------------------------------------------------------------------------
// Prep kernels
// ---------------------------------------------------------------------------
__global__ void init_state(const float* __restrict__ c_in, const float* __restrict__ h_in)
{
    int i = blockIdx.x * blockDim.x + threadIdx.x;
    if (i < BB * HH) {
        g_c[i] = c_in[i];
        float h = h_in[i];
        g_h[i] = h;
        g_h16[0][i] = __float2half(h);
    }
}

__global__ __launch_bounds__(256) void convert_x(const float* __restrict__ x)
{
    size_t i4 = (size_t)blockIdx.x * 256 + threadIdx.x;
    float4 v = *(const float4*)(x + i4 * 4);
    union { h16 h[4]; uint2 u; } H;
    H.h[0] = __float2half(v.x);
    H.h[1] = __float2half(v.y);
    H.h[2] = __float2half(v.z);
    H.h[3] = __float2half(v.w);
    *(uint2*)(g_x16 + i4 * 4) = H.u;
}

// in: [K,N] fp32 -> out rows (interleave ? (c%1024)*4+c/1024 : c). ol optional.
__global__ void transpose_split(const float* __restrict__ in, h16* __restrict__ oh,
                                h16* __restrict__ ol, int K, int N, int interleave)
{
    __shared__ float tile[32][33];
    const int kb = blockIdx.y * 32;
    const int nb = blockIdx.x * 32;
    const int tx = threadIdx.x;
    for (int r = threadIdx.y; r < 32; r += 8)
        tile[r][tx] = in[(size_t)(kb + r) * N + nb + tx];
    __syncthreads();
    for (int rr = threadIdx.y; rr < 32; rr += 8) {
        float v = tile[tx][rr];
        h16 hi, lo;
        splitw(v, hi, lo);
        int c = nb + rr;
        int n_new = interleave ? ((c & 1023) * 4 + (c >> 10)) : c;
        const size_t o = (size_t)n_new * K + kb + tx;
        oh[o] = hi;
        if (ol) ol[o] = lo;
    }
}

__global__ void permute_bias(const float* __restrict__ b)
{
    int c = blockIdx.x * 256 + threadIdx.x;
    if (c < FOURH) g_bias[(c & 1023) * 4 + (c >> 10)] = b[c];
}

// ---------------------------------------------------------------------------
// kernel_launch
// ---------------------------------------------------------------------------
extern "C" void kernel_launch(void* const* d_in, const int* in_sizes, int n_in,
                              void* d_out, int out_size)
{
    const float* X    = (const float*)d_in[0];
    const int*   seq  = (const int*)d_in[1];
    const float* c_in = (const float*)d_in[2];
    const float* h_in = (const float*)d_in[3];
    const float* W    = (const float*)d_in[4];
    const float* bias = (const float*)d_in[5];
    const float* Wout = (const float*)d_in[6];
    const float* bout = (const float*)d_in[7];
    float* out = (float*)d_out;

    float *p_xw, *p_bias;
    h16 *p_x16, *p_f16, *p_wxh, *p_whh, *p_whl, *p_woh;
    cudaGetSymbolAddress((void**)&p_xw, g_xw);
    cudaGetSymbolAddress((void**)&p_bias, g_bias);
    cudaGetSymbolAddress((void**)&p_x16, g_x16);
    cudaGetSymbolAddress((void**)&p_f16, g_f16);
    cudaGetSymbolAddress((void**)&p_wxh, g_wx_hi);
    cudaGetSymbolAddress((void**)&p_whh, g_wh_hi);
    cudaGetSymbolAddress((void**)&p_whl, g_wh_lo);
    cudaGetSymbolAddress((void**)&p_woh, g_wo_hi);

    cudaFuncSetAttribute(gemm_f16x1, cudaFuncAttributeMaxDynamicSharedMemorySize, SMEM_X1);
    cudaFuncSetAttribute(lstm_step_fused, cudaFuncAttributeMaxDynamicSharedMemorySize, SMEM_REC);

    // prep
    init_state<<<(BB * HH + 255) / 256, 256>>>(c_in, h_in);
    convert_x<<<(int)((size_t)BT * FF / 4 / 256), 256>>>(X);
    transpose_split<<<dim3(FOURH / 32, FF / 32), dim3(32, 8)>>>(W, p_wxh, nullptr, FF, FOURH, 1);
    transpose_split<<<dim3(FOURH / 32, HH / 32), dim3(32, 8)>>>(W + (size_t)FF * FOURH, p_whh, p_whl, HH, FOURH, 1);
    transpose_split<<<dim3(NOUT / 32, HH / 32), dim3(32, 8)>>>(Wout, p_woh, nullptr, HH, NOUT, 0);
    permute_bias<<<FOURH / 256, 256>>>(bias);

    // XW = X @ Wx^T + b (interleaved cols), single fp16 term
    gemm_f16x1<<<dim3(FOURH / 128, BT / 128), 256, SMEM_X1>>>(
        p_x16, p_wxh, p_bias, p_xw, FOURH, FF);

    // recurrence (fused GEMM + cell), BM=64, 2-term weights, double-buffered h
    for (int t = 0; t < TT; t++)
        lstm_step_fused<<<dim3(FOURH / 128, BB / 64), 256, SMEM_REC>>>(t, seq);

    // head, single fp16 term
    gemm_f16x1<<<dim3(NOUT / 128, BT / 128), 256, SMEM_X1>>>(
        p_f16, p_woh, bout, out, NOUT, HH);
}

// round 9
// speedup vs baseline: 5.4519x; 1.1529x over previous
#include <cuda_runtime.h>
#include <cuda_fp16.h>
#include <math.h>
#include <stdint.h>

#define BB 512
#define TT 128
#define FF 1024
#define HH 1024
#define NOUT 256
#define FOURH 4096
#define BT 65536

typedef __half h16;

// ---------------------------------------------------------------------------
// Device-global scratch (sorted-batch order unless noted)
// ---------------------------------------------------------------------------
__device__ float g_xw[(size_t)BT * FOURH];     // X @ Wx + b, gate-interleaved cols
__device__ float g_c[BB * HH];
__device__ float g_h[BB * HH];
__device__ float g_bias[FOURH];                // permuted bias
__device__ h16   g_x16[(size_t)BT * FF];       // X as fp16 (ORIGINAL batch order)
__device__ h16   g_f16[(size_t)BT * HH];       // masked h outputs (zero-init!)
__device__ h16   g_h16[2][BB * HH];            // double-buffered h state, fp16
__device__ h16   g_wx_hi[(size_t)FOURH * FF];  // Wx^T [4H,F] K-major, interleaved rows
__device__ h16   g_wh_hi[(size_t)FOURH * HH];
__device__ h16   g_wh_lo[(size_t)FOURH * HH];
__device__ h16   g_wo_hi[NOUT * HH];
__device__ int   g_perm[BB];                   // sorted idx -> original idx
__device__ int   g_seqp[BB];                   // seq_len in sorted order (descending)
__device__ int   g_nact[TT];                   // #batches with seq_len > t

// ---------------------------------------------------------------------------
// Baseline-PTX helpers (legal on plain sm_103 target)
// ---------------------------------------------------------------------------
__device__ __forceinline__ uint32_t smem_u32(const void* p) {
    uint32_t a;
    asm("{ .reg .u64 t; cvta.to.shared.u64 t, %1; cvt.u32.u64 %0, t; }"
        : "=r"(a) : "l"(p));
    return a;
}
__device__ __forceinline__ void cp16(uint32_t dst, const void* src) {
    asm volatile("cp.async.cg.shared.global [%0], [%1], 16;"
                 :: "r"(dst), "l"(src) : "memory");
}
__device__ __forceinline__ void ldsm4(uint32_t* r, uint32_t addr) {
    asm volatile("ldmatrix.sync.aligned.m8n8.x4.shared.b16 {%0,%1,%2,%3}, [%4];"
                 : "=r"(r[0]), "=r"(r[1]), "=r"(r[2]), "=r"(r[3]) : "r"(addr));
}
__device__ __forceinline__ void mma16816(float* d, const uint32_t* a, const uint32_t* b) {
    asm volatile(
        "mma.sync.aligned.m16n8k16.row.col.f32.f16.f16.f32 "
        "{%0,%1,%2,%3}, {%4,%5,%6,%7}, {%8,%9}, {%0,%1,%2,%3};"
        : "+f"(d[0]), "+f"(d[1]), "+f"(d[2]), "+f"(d[3])
        : "r"(a[0]), "r"(a[1]), "r"(a[2]), "r"(a[3]), "r"(b[0]), "r"(b[1]));
}

// ---------------------------------------------------------------------------
// GEMM tile machinery. BN=128, BK=32, 256 threads (8 warps 2x4).
// BM = MT*32. NB = B terms. NST = stages. A pointer pre-offset (row 0 = tile top).
// ---------------------------------------------------------------------------
#define ROWB 80
#define OP_BYTES (128 * ROWB)              // 10240

template <int MT, int NB>
__device__ __forceinline__ void load_stage(
    uint32_t stg, const h16* __restrict__ A,
    const h16* __restrict__ Bh, const h16* __restrict__ Bl,
    int n0, int k0, int K, int tid)
{
    constexpr int BM = MT * 32;
    constexpr uint32_t OFFB = (uint32_t)BM * ROWB;
#pragma unroll
    for (int i = 0; i < BM * 4 / 256; i++) {
        const int c = tid + i * 256;
        const int row = c >> 2;
        const int seg = c & 3;
        cp16(stg + (uint32_t)(row * ROWB + seg * 16),
             A + (size_t)row * K + k0 + seg * 8);
    }
#pragma unroll
    for (int i = 0; i < 2; i++) {
        const int c = tid + i * 256;
        const int row = c >> 2;
        const int seg = c & 3;
        const uint32_t soff = (uint32_t)(row * ROWB + seg * 16);
        const size_t gb = (size_t)(n0 + row) * K + k0 + seg * 8;
        cp16(stg + OFFB + soff, Bh + gb);
        if (NB == 2) cp16(stg + OFFB + OP_BYTES + soff, Bl + gb);
    }
}

template <int MT, int NB, int NST>
__device__ __forceinline__ void gemm_mainloop(
    uint32_t SM, const h16* __restrict__ A,
    const h16* __restrict__ Bh, const h16* __restrict__ Bl,
    int n0, int K, int tid, float acc[MT][4][4])
{
    constexpr uint32_t OFFB = (uint32_t)(MT * 32) * ROWB;
    constexpr uint32_t STG_B = OFFB + NB * OP_BYTES;
    const int lane = tid & 31;
    const int wid  = tid >> 5;
    const int wm   = wid & 1;
    const int wn   = wid >> 1;
    const int NC = K >> 5;

#pragma unroll
    for (int s = 0; s < NST - 1; s++) {
        load_stage<MT, NB>(SM + s * STG_B, A, Bh, Bl, n0, s * 32, K, tid);
        asm volatile("cp.async.commit_group;" ::: "memory");
    }

    const int arow = wm * (MT * 16) + (lane & 15);
    const uint32_t akoff = (uint32_t)((lane >> 4) * 16);
    const int bsel = lane >> 3;
    const int bn = wn * 32 + ((bsel >> 1) << 3) + (lane & 7);
    const uint32_t bkoff = (uint32_t)((bsel & 1) * 16);

    for (int it = 0; it < NC; it++) {
        asm volatile("cp.async.wait_group %0;" :: "n"(NST - 2) : "memory");
        __syncthreads();

        const int nx = it + NST - 1;
        if (nx < NC)
            load_stage<MT, NB>(SM + (uint32_t)(nx % NST) * STG_B,
                               A, Bh, Bl, n0, nx * 32, K, tid);
        asm volatile("cp.async.commit_group;" ::: "memory");

        const uint32_t stg = SM + (uint32_t)(it % NST) * STG_B;
#pragma unroll
        for (int ks = 0; ks < 2; ks++) {
            uint32_t ah[MT][4], bh[4][2], bl[4][2];
            const uint32_t ak = (uint32_t)(ks * 32) + akoff;
#pragma unroll
            for (int mt = 0; mt < MT; mt++)
                ldsm4(ah[mt], stg + (uint32_t)((arow + mt * 16) * ROWB) + ak);
            const uint32_t bk = (uint32_t)(ks * 32) + bkoff;
#pragma unroll
            for (int np = 0; np < 2; np++) {
                const uint32_t bd = stg + OFFB + (uint32_t)((bn + np * 16) * ROWB) + bk;
                uint32_t tr[4];
                ldsm4(tr, bd);
                bh[2 * np][0] = tr[0]; bh[2 * np][1] = tr[1];
                bh[2 * np + 1][0] = tr[2]; bh[2 * np + 1][1] = tr[3];
                if (NB == 2) {
                    ldsm4(tr, bd + OP_BYTES);
                    bl[2 * np][0] = tr[0]; bl[2 * np][1] = tr[1];
                    bl[2 * np + 1][0] = tr[2]; bl[2 * np + 1][1] = tr[3];
                }
            }
#pragma unroll
            for (int mt = 0; mt < MT; mt++)
#pragma unroll
                for (int nt = 0; nt < 4; nt++) {
                    mma16816(acc[mt][nt], ah[mt], bh[nt]);
                    if (NB == 2) mma16816(acc[mt][nt], ah[mt], bl[nt]);
                }
        }
    }
}

// Common epilogue: acc -> C (row-stride N) with optional bias indexed by n0+col.
template <int MT>
__device__ __forceinline__ void store_acc(
    float acc[MT][4][4], float* __restrict__ C, const float* __restrict__ bias,
    int N, int n0, int tid)
{
    const int lane = tid & 31;
    const int wid  = tid >> 5;
    const int wm   = wid & 1;
    const int wn   = wid >> 1;
    const int colq = (lane & 3) * 2;
    const int rowq = lane >> 2;
#pragma unroll
    for (int nt = 0; nt < 4; nt++) {
        const int col = wn * 32 + nt * 8 + colq;
        float bx = 0.f, by = 0.f;
        if (bias) { float2 bv = *(const float2*)(bias + n0 + col); bx = bv.x; by = bv.y; }
#pragma unroll
        for (int mt = 0; mt < MT; mt++) {
            const int r0 = wm * (MT * 16) + mt * 16 + rowq;
            *(float2*)(C + (size_t)r0 * N + n0 + col) =
                make_float2(acc[mt][nt][0] + bx, acc[mt][nt][1] + by);
            *(float2*)(C + (size_t)(r0 + 8) * N + n0 + col) =
                make_float2(acc[mt][nt][2] + bx, acc[mt][nt][3] + by);
        }
    }
}

// ---------------------------------------------------------------------------
// XW GEMM: BM=64 tiles over (batch, 64-step t-range); skip if t0 >= seq.
// Reads X in original order (via perm), writes g_xw in sorted order.
// ---------------------------------------------------------------------------
#define SMEM_X (4 * (64 * ROWB + OP_BYTES))     // 4 stages * 15360 = 61440
__global__ __launch_bounds__(256, 2)
void gemm_xw()
{
    extern __shared__ char smem_raw[];
    const uint32_t SM = smem_u32(smem_raw);
    const int tid = threadIdx.x;
    const int my = blockIdx.y;
    const int bp = my >> 1;
    const int t0 = (my & 1) * 64;
    if (t0 >= g_seqp[bp]) return;
    const int n0 = blockIdx.x * 128;

    const h16* A = g_x16 + ((size_t)g_perm[bp] * TT + t0) * FF;
    float* C = g_xw + ((size_t)bp * TT + t0) * FOURH;

    float acc[2][4][4];
#pragma unroll
    for (int a = 0; a < 2; a++)
#pragma unroll
        for (int b = 0; b < 4; b++)
#pragma unroll
            for (int cc = 0; cc < 4; cc++) acc[a][b][cc] = 0.0f;

    gemm_mainloop<2, 1, 4>(SM, A, g_wx_hi, nullptr, n0, FF, tid, acc);
    store_acc<2>(acc, C, g_bias, FOURH, n0, tid);
}

// ---------------------------------------------------------------------------
// Head GEMM: BM=64 tiles; skipped tiles emit bias rows. Output in ORIGINAL order.
// ---------------------------------------------------------------------------
__global__ __launch_bounds__(256, 2)
void gemm_head(const float* __restrict__ bout, float* __restrict__ out)
{
    extern __shared__ char smem_raw[];
    const uint32_t SM = smem_u32(smem_raw);
    const int tid = threadIdx.x;
    const int my = blockIdx.y;
    const int bp = my >> 1;
    const int t0 = (my & 1) * 64;
    const int n0 = blockIdx.x * 128;
    float* C = out + ((size_t)g_perm[bp] * TT + t0) * NOUT;

    if (t0 >= g_seqp[bp]) {
        // feats are exactly zero here -> logits = bias. Write our 64x128 slice.
#pragma unroll
        for (int i = 0; i < 8; i++) {
            const int idx = i * 256 + tid;      // 2048 float4 slots = 64 rows x 32
            const int r = idx >> 5;
            const int c = (idx & 31) * 4;
            *(float4*)(C + (size_t)r * NOUT + n0 + c) = *(const float4*)(bout + n0 + c);
        }
        return;
    }

    const h16* A = g_f16 + ((size_t)bp * TT + t0) * HH;
    float acc[2][4][4];
#pragma unroll
    for (int a = 0; a < 2; a++)
#pragma unroll
        for (int b = 0; b < 4; b++)
#pragma unroll
            for (int cc = 0; cc < 4; cc++) acc[a][b][cc] = 0.0f;

    gemm_mainloop<2, 1, 4>(SM, A, g_wo_hi, nullptr, n0, HH, tid, acc);
    store_acc<2>(acc, C, bout, NOUT, n0, tid);
}

// ---------------------------------------------------------------------------
// Fused recurrent step: BM=64, 2-term weights, 3 stages, prefix-active skip.
// ---------------------------------------------------------------------------
#define SMEM_REC (3 * (64 * ROWB + 2 * OP_BYTES))   // 3 * 25600 = 76800
__device__ __forceinline__ float sigf(float x) { return 1.0f / (1.0f + expf(-x)); }
__device__ __forceinline__ void splitw(float v, h16& hi, h16& lo) {
    hi = __float2half(v);
    lo = __float2half(v - __half2float(hi));
}

#define ZPITCH 132

__global__ __launch_bounds__(256, 2)
void lstm_step_fused(int t)
{
    const int m0 = blockIdx.y * 64;
    if (m0 >= g_nact[t]) return;            // whole tile past seq end

    extern __shared__ char smem_raw[];
    const uint32_t SM = smem_u32(smem_raw);
    float* zs = (float*)smem_raw;
    const int tid  = threadIdx.x;
    const int lane = tid & 31;
    const int wid  = tid >> 5;
    const int wm   = wid & 1;
    const int wn   = wid >> 1;
    const int n0 = blockIdx.x * 128;

    const h16* __restrict__ h_rd = g_h16[t & 1] + (size_t)m0 * HH;
    h16* __restrict__ h_wr = g_h16[(t + 1) & 1];

    float acc[2][4][4];
#pragma unroll
    for (int a = 0; a < 2; a++)
#pragma unroll
        for (int b = 0; b < 4; b++)
#pragma unroll
            for (int cc = 0; cc < 4; cc++) acc[a][b][cc] = 0.0f;

    gemm_mainloop<2, 2, 3>(SM, h_rd, g_wh_hi, g_wh_lo, n0, HH, tid, acc);

    __syncthreads();

    const int colq = (lane & 3) * 2;
    const int rowq = lane >> 2;
#pragma unroll
    for (int nt = 0; nt < 4; nt++) {
        const int col = wn * 32 + nt * 8 + colq;
#pragma unroll
        for (int mt = 0; mt < 2; mt++) {
            const int r0 = wm * 32 + mt * 16 + rowq;
            *(float2*)&zs[r0 * ZPITCH + col] = make_float2(acc[mt][nt][0], acc[mt][nt][1]);
            *(float2*)&zs[(r0 + 8) * ZPITCH + col] = make_float2(acc[mt][nt][2], acc[mt][nt][3]);
        }
    }
    __syncthreads();

#pragma unroll
    for (int i = 0; i < 8; i++) {
        const int idx = i * 256 + tid;
        const int r = idx >> 5;
        const int u = idx & 31;
        const int b = m0 + r;                // sorted batch index
        const int hx = (n0 >> 2) + u;

        float4 z4 = *(float4*)&zs[r * ZPITCH + 4 * u];
        float4 x4 = *(const float4*)(g_xw + ((size_t)b * TT + t) * FOURH + n0 + 4 * u);

        const float zi = z4.x + x4.x;
        const float zj = z4.y + x4.y;
        const float zf = z4.z + x4.z;
        const float zo = z4.w + x4.w;

        const size_t si = (size_t)b * HH + hx;
        const float c = g_c[si];
        const float hprev = g_h[si];
        const bool m = t < g_seqp[b];

        const float nc = c * sigf(zf + 1.0f) + sigf(zi) * tanhf(zj);
        const float nh = tanhf(nc) * sigf(zo);

        const float co = m ? nc : c;
        const float ho = m ? nh : hprev;
        const float fe = m ? nh : 0.0f;

        g_c[si] = co;
        g_h[si] = ho;
        h_wr[si] = __float2half(ho);
        g_f16[((size_t)b * TT + t) * HH + hx] = __float2half(fe);
    }
}

// ---------------------------------------------------------------------------
// Prep kernels
// ---------------------------------------------------------------------------
__global__ void sort_batches(const int* __restrict__ seq)
{
    __shared__ int hist[130];
    __shared__ int off[130];
    const int tid = threadIdx.x;
    if (tid < 130) hist[tid] = 0;
    __syncthreads();
    for (int b = tid; b < BB; b += 256) atomicAdd(&hist[seq[b]], 1);
    __syncthreads();
    if (tid == 0) {
        int acc = 0;
        for (int v = 128; v >= 1; v--) { off[v] = acc; acc += hist[v]; }
    }
    __syncthreads();
    if (tid < TT) g_nact[tid] = (tid == 0) ? BB : off[tid];   // #seq > t
    __syncthreads();
    if (tid == 0) {
        for (int b = 0; b < BB; b++) {
            const int v = seq[b];
            const int p = off[v]++;
            g_perm[p] = b;
            g_seqp[p] = v;
        }
    }
}

__global__ void init_state(const float* __restrict__ c_in, const float* __restrict__ h_in)
{
    int i = blockIdx.x * blockDim.x + threadIdx.x;
    if (i < BB * HH) {
        const int bp = i / HH;
        const int hx = i - bp * HH;
        const size_t src = (size_t)g_perm[bp] * HH + hx;
        g_c[i] = c_in[src];
        float h = h_in[src];
        g_h[i] = h;
        g_h16[0][i] = __float2half(h);
    }
}

__global__ __launch_bounds__(256) void convert_x(const float* __restrict__ x)
{
    size_t i4 = (size_t)blockIdx.x * 256 + threadIdx.x;
    float4 v = *(const float4*)(x + i4 * 4);
    union { h16 h[4]; uint2 u; } H;
    H.h[0] = __float2half(v.x);
    H.h[1] = __float2half(v.y);
    H.h[2] = __float2half(v.z);
    H.h[3] = __float2half(v.w);
    *(uint2*)(g_x16 + i4 * 4) = H.u;
}

// in: [K,N] fp32 -> out rows (interleave ? (c%1024)*4+c/1024 : c). ol optional.
__global__ void transpose_split(const float* __restrict__ in, h16* __restrict__ oh,
                                h16* __restrict__ ol, int K, int N, int interleave)
{
    __shared__ float tile[32][33];
    const int kb = blockIdx.y * 32;
    const int nb = blockIdx.x * 32;
    const int tx = threadIdx.x;
    for (int r = threadIdx.y; r < 32; r += 8)
        tile[r][tx] = in[(size_t)(kb + r) * N + nb + tx];
    __syncthreads();
    for (int rr = threadIdx.y; rr < 32; rr += 8) {
        float v = tile[tx][rr];
        h16 hi, lo;
        splitw(v, hi, lo);
        int c = nb + rr;
        int n_new = interleave ? ((c & 1023) * 4 + (c >> 10)) : c;
        const size_t o = (size_t)n_new * K + kb + tx;
        oh[o] = hi;
        if (ol) ol[o] = lo;
    }
}

__global__ void permute_bias(const float* __restrict__ b)
{
    int c = blockIdx.x * 256 + threadIdx.x;
    if (c < FOURH) g_bias[(c & 1023) * 4 + (c >> 10)] = b[c];
}

// ---------------------------------------------------------------------------
// kernel_launch
// ---------------------------------------------------------------------------
extern "C" void kernel_launch(void* const* d_in, const int* in_sizes, int n_in,
                              void* d_out, int out_size)
{
    const float* X    = (const float*)d_in[0];
    const int*   seq  = (const int*)d_in[1];
    const float* c_in = (const float*)d_in[2];
    const float* h_in = (const float*)d_in[3];
    const float* W    = (const float*)d_in[4];
    const float* bias = (const float*)d_in[5];
    const float* Wout = (const float*)d_in[6];
    const float* bout = (const float*)d_in[7];
    float* out = (float*)d_out;

    h16 *p_wxh, *p_whh, *p_whl, *p_woh;
    cudaGetSymbolAddress((void**)&p_wxh, g_wx_hi);
    cudaGetSymbolAddress((void**)&p_whh, g_wh_hi);
    cudaGetSymbolAddress((void**)&p_whl, g_wh_lo);
    cudaGetSymbolAddress((void**)&p_woh, g_wo_hi);

    cudaFuncSetAttribute(gemm_xw, cudaFuncAttributeMaxDynamicSharedMemorySize, SMEM_X);
    cudaFuncSetAttribute(gemm_head, cudaFuncAttributeMaxDynamicSharedMemorySize, SMEM_X);
    cudaFuncSetAttribute(lstm_step_fused, cudaFuncAttributeMaxDynamicSharedMemorySize, SMEM_REC);

    // prep
    sort_batches<<<1, 256>>>(seq);
    init_state<<<(BB * HH + 255) / 256, 256>>>(c_in, h_in);
    convert_x<<<(int)((size_t)BT * FF / 4 / 256), 256>>>(X);
    transpose_split<<<dim3(FOURH / 32, FF / 32), dim3(32, 8)>>>(W, p_wxh, nullptr, FF, FOURH, 1);
    transpose_split<<<dim3(FOURH / 32, HH / 32), dim3(32, 8)>>>(W + (size_t)FF * FOURH, p_whh, p_whl, HH, FOURH, 1);
    transpose_split<<<dim3(NOUT / 32, HH / 32), dim3(32, 8)>>>(Wout, p_woh, nullptr, HH, NOUT, 0);
    permute_bias<<<FOURH / 256, 256>>>(bias);

    // XW (skip tiles fully past seq end)
    gemm_xw<<<dim3(FOURH / 128, BT / 64), 256, SMEM_X>>>();

    // recurrence: prefix-active tiles only
    for (int t = 0; t < TT; t++)
        lstm_step_fused<<<dim3(FOURH / 128, BB / 64), 256, SMEM_REC>>>(t);

    // head (skipped tiles write bias rows)
    gemm_head<<<dim3(NOUT / 128, BT / 64), 256, SMEM_X>>>(bout, out);
}